// round 13
// baseline (speedup 1.0000x reference)
#include <cuda_runtime.h>
#include <cuda_bf16.h>
#include <cstdint>

static constexpr int BATCH = 16;
static constexpr int CCH   = 512;
static constexpr int NPIX  = 4096;
static constexpr int HD    = 128;

// fp32 logits (pre-softmax) for A (idx 0) and C (idx 1)
__device__ float g_logits[(size_t)2 * BATCH * HD * NPIX];
// bf16 hi/lo operand stores (as u32 pair arrays)
__device__ uint32_t g_WH[3 * HD * CCH / 2],        g_WL[3 * HD * CCH / 2];
__device__ uint32_t g_BfH[(size_t)BATCH * HD * NPIX / 2],  g_BfL[(size_t)BATCH * HD * NPIX / 2];
__device__ uint32_t g_AmH[(size_t)BATCH * HD * NPIX / 2],  g_AmL[(size_t)BATCH * HD * NPIX / 2];
__device__ uint32_t g_CsH[(size_t)BATCH * HD * NPIX / 2],  g_CsL[(size_t)BATCH * HD * NPIX / 2];
__device__ uint32_t g_M2H[BATCH * CCH * HD / 2],   g_M2L[BATCH * CCH * HD / 2];
__device__ float g_G[BATCH * HD * HD];
__device__ float g_s[CCH];
__device__ float g_t[CCH];

// ---------------------------------------------------------------------------
__device__ __forceinline__ uint32_t smem_u32(const void* p) {
    uint32_t a;
    asm("{ .reg .u64 t; cvta.to.shared.u64 t, %1; cvt.u32.u64 %0, t; }" : "=r"(a) : "l"(p));
    return a;
}
__device__ __forceinline__ void bsplit(float x, __nv_bfloat16& h, __nv_bfloat16& l) {
    h = __float2bfloat16_rn(x);
    l = __float2bfloat16_rn(x - __bfloat162float(h));
}
__device__ __forceinline__ uint32_t packpair(__nv_bfloat16 a, __nv_bfloat16 b) {
    uint16_t au = *(uint16_t*)&a, bu = *(uint16_t*)&b;
    return (uint32_t)au | ((uint32_t)bu << 16);
}
__device__ __forceinline__ void cp16(uint32_t dst, const void* src) {
    asm volatile("cp.async.cg.shared.global [%0], [%1], 16;" :: "r"(dst), "l"(src));
}
#define SW128(off) ((off) ^ (((off) >> 3) & 0x70))

__device__ __forceinline__ void ldsm4(uint32_t (&r)[4], uint32_t addr) {
    asm volatile("ldmatrix.sync.aligned.m8n8.x4.shared.b16 {%0,%1,%2,%3}, [%4];"
                 : "=r"(r[0]), "=r"(r[1]), "=r"(r[2]), "=r"(r[3]) : "r"(addr));
}
__device__ __forceinline__ void ldsm4t(uint32_t (&r)[4], uint32_t addr) {
    asm volatile("ldmatrix.sync.aligned.m8n8.x4.trans.shared.b16 {%0,%1,%2,%3}, [%4];"
                 : "=r"(r[0]), "=r"(r[1]), "=r"(r[2]), "=r"(r[3]) : "r"(addr));
}
__device__ __forceinline__ void mma16(float4& d, const uint32_t* a, uint32_t b0, uint32_t b1) {
    asm volatile("mma.sync.aligned.m16n8k16.row.col.f32.bf16.bf16.f32 "
                 "{%0,%1,%2,%3},{%4,%5,%6,%7},{%8,%9},{%0,%1,%2,%3};"
                 : "+f"(d.x), "+f"(d.y), "+f"(d.z), "+f"(d.w)
                 : "r"(a[0]), "r"(a[1]), "r"(a[2]), "r"(a[3]), "r"(b0), "r"(b1));
}

// ---------------------------------------------------------------------------
// generic compute core (R12): NP n16-groups per warp, BK=64
// ---------------------------------------------------------------------------
static constexpr int SLAB_A = 16384;   // 128 rows x 128B

template<int NP, bool TRB>
__device__ __forceinline__ void compute_tile2(
    uint32_t abase, uint32_t ahalfoff,
    uint32_t bbase, uint32_t bhalfoff, int bchstride, int browoff,
    int lane, int wm, int wn, float4 (&acc)[2][NP][2]) {
    const int rl = lane & 15, gh = lane >> 4;
    constexpr int WN = NP * 16;

    uint32_t aH[2][2][4], aL[2][2][4];
    uint32_t bh[2][4], bl[2][4];

    auto loadA = [&](int ks, int buf) {
#pragma unroll
        for (int mt = 0; mt < 2; mt++) {
            uint32_t ar = abase + SW128((wm * 32 + mt * 16 + rl) * 128 + (ks * 2 + gh) * 16);
            ldsm4(aH[buf][mt], ar);
            ldsm4(aL[buf][mt], ar + ahalfoff);
        }
    };
    auto loadB = [&](int ks, int ntp, int buf) {
        if (!TRB) {
            uint32_t br = bbase + SW128((wn * WN + ntp * 16 + rl) * 128 + (ks * 2 + gh) * 16);
            ldsm4(bh[buf], br);
            ldsm4(bl[buf], br + bhalfoff);
        } else {
            int n = wn * WN + ntp * 16 + gh * 8;
            int chunk = n >> 6, col16 = (n & 63) >> 3;
            uint32_t br = bbase + chunk * bchstride +
                          SW128((browoff + ks * 16 + rl) * 128 + col16 * 16);
            ldsm4t(bh[buf], br);
            ldsm4t(bl[buf], br + bhalfoff);
        }
    };

    loadA(0, 0);
    loadB(0, 0, 0);
#pragma unroll
    for (int ks = 0; ks < 4; ks++) {
        const int ab = ks & 1;
#pragma unroll
        for (int ntp = 0; ntp < NP; ntp++) {
            const int bb = (ks * NP + ntp) & 1;
            if (ntp + 1 < NP) {
                loadB(ks, ntp + 1, (ks * NP + ntp + 1) & 1);
            } else if (ks + 1 < 4) {
                loadA(ks + 1, (ks + 1) & 1);
                loadB(ks + 1, 0, ((ks + 1) * NP) & 1);
            }
            uint32_t b0h[2], b1h[2], b0l[2], b1l[2];
#pragma unroll
            for (int j = 0; j < 2; j++) {
                b0h[j] = TRB ? bh[bb][2 * j]     : bh[bb][j];
                b1h[j] = TRB ? bh[bb][2 * j + 1] : bh[bb][j + 2];
                b0l[j] = TRB ? bl[bb][2 * j]     : bl[bb][j];
                b1l[j] = TRB ? bl[bb][2 * j + 1] : bl[bb][j + 2];
            }
#pragma unroll
            for (int j = 0; j < 2; j++)
#pragma unroll
                for (int mt = 0; mt < 2; mt++)
                    mma16(acc[mt][ntp][j], aH[ab][mt], b0h[j], b1h[j]);
#pragma unroll
            for (int j = 0; j < 2; j++)
#pragma unroll
                for (int mt = 0; mt < 2; mt++)
                    mma16(acc[mt][ntp][j], aH[ab][mt], b0l[j], b1l[j]);
#pragma unroll
            for (int j = 0; j < 2; j++)
#pragma unroll
                for (int mt = 0; mt < 2; mt++)
                    mma16(acc[mt][ntp][j], aL[ab][mt], b0h[j], b1h[j]);
        }
    }
}

// k1 variant: NP=4, TRB, A single-buffered (register budget), B double-buffered
template<int NP>
__device__ __forceinline__ void compute_tile_k1(
    uint32_t abase, uint32_t bbase, uint32_t bhalfoff, int bchstride,
    int lane, int wm, int wn, float4 (&acc)[2][NP][2]) {
    const int rl = lane & 15, gh = lane >> 4;
    constexpr int WN = NP * 16;

    uint32_t aH[2][4], aL[2][4];
    uint32_t bh[2][4], bl[2][4];

    auto loadA = [&](int ks) {
#pragma unroll
        for (int mt = 0; mt < 2; mt++) {
            uint32_t ar = abase + SW128((wm * 32 + mt * 16 + rl) * 128 + (ks * 2 + gh) * 16);
            ldsm4(aH[mt], ar);
            ldsm4(aL[mt], ar + SLAB_A);
        }
    };
    auto loadB = [&](int ks, int ntp, int buf) {
        int n = wn * WN + ntp * 16 + gh * 8;
        int chunk = n >> 6, col16 = (n & 63) >> 3;
        uint32_t br = bbase + chunk * bchstride + SW128((ks * 16 + rl) * 128 + col16 * 16);
        ldsm4t(bh[buf], br);
        ldsm4t(bl[buf], br + bhalfoff);
    };

    loadB(0, 0, 0);
#pragma unroll
    for (int ks = 0; ks < 4; ks++) {
        loadA(ks);
#pragma unroll
        for (int ntp = 0; ntp < NP; ntp++) {
            const int bb = (ks * NP + ntp) & 1;
            if (ntp + 1 < NP)
                loadB(ks, ntp + 1, (ks * NP + ntp + 1) & 1);
            else if (ks + 1 < 4)
                loadB(ks + 1, 0, ((ks + 1) * NP) & 1);
            uint32_t b0h[2] = {bh[bb][0], bh[bb][2]}, b1h[2] = {bh[bb][1], bh[bb][3]};
            uint32_t b0l[2] = {bl[bb][0], bl[bb][2]}, b1l[2] = {bl[bb][1], bl[bb][3]};
#pragma unroll
            for (int j = 0; j < 2; j++)
#pragma unroll
                for (int mt = 0; mt < 2; mt++)
                    mma16(acc[mt][ntp][j], aH[mt], b0h[j], b1h[j]);
#pragma unroll
            for (int j = 0; j < 2; j++)
#pragma unroll
                for (int mt = 0; mt < 2; mt++)
                    mma16(acc[mt][ntp][j], aH[mt], b0l[j], b1l[j]);
#pragma unroll
            for (int j = 0; j < 2; j++)
#pragma unroll
                for (int mt = 0; mt < 2; mt++)
                    mma16(acc[mt][ntp][j], aL[mt], b0h[j], b1h[j]);
        }
    }
}

// ---------------------------------------------------------------------------
// smem tile loader for k3 (NN=128, k-major B)
// ---------------------------------------------------------------------------
template<int NN>
struct GeomT {
    static constexpr int WN    = NN / 4;
    static constexpr int NP16  = WN / 16;
    static constexpr int BUF   = 2 * SLAB_A + 2 * NN * 128;
    static constexpr int ITER  = (256 + 2 * NN) / 64;
};

template<int NN, bool TRB>
__device__ __forceinline__ void load_tile(uint32_t bufb, int kofs,
                                          const __nv_bfloat16* aH, const __nv_bfloat16* aL, int sA,
                                          const __nv_bfloat16* bH, const __nv_bfloat16* bL, int sB) {
    const int tid = threadIdx.x;
#pragma unroll
    for (int i = 0; i < GeomT<NN>::ITER; i++) {
        int g = tid + i * 512;
        if (g < 2048) {
            int row_lin = g >> 3, gran = g & 7;
            const __nv_bfloat16* s = (row_lin < 128) ? aH : aL;
            int row = row_lin & 127;
            uint32_t slaboff = (row_lin < 128) ? 0u : (uint32_t)SLAB_A;
            cp16(bufb + slaboff + SW128(row * 128 + gran * 16),
                 s + (size_t)row * sA + kofs + gran * 8);
        } else {
            int g2 = g - 2048;
            int half = g2 / (NN * 8);
            int g3 = g2 % (NN * 8);
            const __nv_bfloat16* s = half ? bL : bH;
            uint32_t slaboff = 2 * SLAB_A + (uint32_t)half * NN * 128;
            if (!TRB) {
                int row = g3 >> 3, gran = g3 & 7;
                cp16(bufb + slaboff + SW128(row * 128 + gran * 16),
                     s + (size_t)row * sB + kofs + gran * 8);
            } else {
                int krow = g3 >> 5, g32 = g3 & 31;
                int chunk = g32 >> 3, col16 = g32 & 7;
                cp16(bufb + slaboff + chunk * 8192 + SW128(krow * 128 + col16 * 16),
                     s + (size_t)(kofs + krow) * sB + g32 * 8);
            }
        }
    }
    asm volatile("cp.async.commit_group;" ::: "memory");
}

template<int NN, bool TRB>
__device__ __forceinline__ void run_gemm(uint32_t sbase, int KT,
                                         const __nv_bfloat16* aH, const __nv_bfloat16* aL, int sA,
                                         const __nv_bfloat16* bH, const __nv_bfloat16* bL, int sB,
                                         float4 (&acc)[2][GeomT<NN>::NP16][2]) {
    const int tid = threadIdx.x;
    const int lane = tid & 31, wid = tid >> 5;
    const int wm = wid & 3, wn = wid >> 2;

    load_tile<NN, TRB>(sbase, 0, aH, aL, sA, bH, bL, sB);
    for (int kt = 0; kt < KT; kt++) {
        asm volatile("cp.async.wait_group 0;" ::: "memory");
        __syncthreads();
        if (kt + 1 < KT)
            load_tile<NN, TRB>(sbase + ((kt + 1) & 1) * GeomT<NN>::BUF, (kt + 1) * 64,
                               aH, aL, sA, bH, bL, sB);
        uint32_t bufb = sbase + (kt & 1) * GeomT<NN>::BUF;
        compute_tile2<GeomT<NN>::NP16, TRB>(bufb, SLAB_A,
                                            bufb + 2 * SLAB_A, (uint32_t)(NN * 128),
                                            8192, 0, lane, wm, wn, acc);
    }
}

// ---------------------------------------------------------------------------
// prep
// ---------------------------------------------------------------------------
__global__ void __launch_bounds__(256) k_prep(const float* __restrict__ gamma,
                                              const float* __restrict__ beta,
                                              const float* __restrict__ mean,
                                              const float* __restrict__ var,
                                              const float* __restrict__ wA,
                                              const float* __restrict__ wB,
                                              const float* __restrict__ wC) {
    int idx = blockIdx.x * 256 + threadIdx.x;
    if (idx < BATCH * HD * HD) g_G[idx] = 0.0f;
    if (idx < CCH) {
        float inv = rsqrtf(var[idx] + 1e-5f);
        float sc  = inv * gamma[idx];
        g_s[idx] = sc;
        g_t[idx] = beta[idx] - mean[idx] * sc;
    }
    if (idx < 3 * HD * CCH / 2) {
        const float* src = (idx < 32768) ? wA : (idx < 65536) ? wB : wC;
        int lp = idx & 32767;
        float f0 = src[2 * lp], f1 = src[2 * lp + 1];
        __nv_bfloat16 h0, l0, h1, l1;
        bsplit(f0, h0, l0); bsplit(f1, h1, l1);
        g_WH[idx] = packpair(h0, h1);
        g_WL[idx] = packpair(l0, l1);
    }
}

// ---------------------------------------------------------------------------
// K1: logits = W[w] @ x[b], NN=256 (warp tile 32x64), direct-x fused split.
// x staged in two 16-float halves to bound registers.
// ---------------------------------------------------------------------------
static constexpr int K1BUF = 2 * SLAB_A + 2 * 256 * 128;   // 96 KB per stage

__device__ __forceinline__ void k1_load_A(uint32_t bufb, int kofs,
                                          const __nv_bfloat16* aH, const __nv_bfloat16* aL) {
    const int tid = threadIdx.x;
#pragma unroll
    for (int i = 0; i < 4; i++) {
        int g = tid + i * 512;
        int row_lin = g >> 3, gran = g & 7;
        const __nv_bfloat16* s = (row_lin < 128) ? aH : aL;
        int row = row_lin & 127;
        uint32_t slaboff = (row_lin < 128) ? 0u : (uint32_t)SLAB_A;
        cp16(bufb + slaboff + SW128(row * 128 + gran * 16),
             s + (size_t)row * CCH + kofs + gran * 8);
    }
    asm volatile("cp.async.commit_group;" ::: "memory");
}

// load 64 k-rows x 128 n (half of the 256-wide tile)
__device__ __forceinline__ void k1_ldg_B(float (&st)[16], const float* xb, int kofs, int half) {
    const int tid = threadIdx.x;
#pragma unroll
    for (int i = 0; i < 4; i++) {
        int idx = tid + i * 512;
        int krow = idx >> 5, ng4 = idx & 31;
        const float* p = xb + (size_t)(kofs + krow) * NPIX + half * 128 + ng4 * 4;
        asm volatile("ld.global.nc.v4.f32 {%0,%1,%2,%3}, [%4];"
                     : "=f"(st[4 * i]), "=f"(st[4 * i + 1]),
                       "=f"(st[4 * i + 2]), "=f"(st[4 * i + 3]) : "l"(p));
    }
}

__device__ __forceinline__ void k1_sts_B(uint32_t bufb, const float (&st)[16], int half) {
    const int tid = threadIdx.x;
    const uint32_t bsb = bufb + 2 * SLAB_A;
#pragma unroll
    for (int i = 0; i < 4; i++) {
        int idx = tid + i * 512;
        int krow = idx >> 5, ng4 = idx & 31;
        int n = half * 128 + ng4 * 4;
        int chunk = n >> 6;
        uint32_t off = bsb + chunk * 8192 + SW128((uint32_t)(krow * 128 + (n & 63) * 2));
        __nv_bfloat16 h0, l0, h1, l1, h2, l2, h3, l3;
        bsplit(st[4 * i],     h0, l0);
        bsplit(st[4 * i + 1], h1, l1);
        bsplit(st[4 * i + 2], h2, l2);
        bsplit(st[4 * i + 3], h3, l3);
        uint32_t hi01 = packpair(h0, h1), hi23 = packpair(h2, h3);
        uint32_t lo01 = packpair(l0, l1), lo23 = packpair(l2, l3);
        asm volatile("st.shared.v2.u32 [%0], {%1,%2};"
                     :: "r"(off), "r"(hi01), "r"(hi23) : "memory");
        asm volatile("st.shared.v2.u32 [%0], {%1,%2};"
                     :: "r"(off + 256 * 128), "r"(lo01), "r"(lo23) : "memory");
    }
}

__global__ void __launch_bounds__(512) k1_gemm(const float* __restrict__ x) {
    extern __shared__ uint32_t smem[];
    uint32_t sbase = smem_u32(smem);
    const int b = blockIdx.z;
    const int w  = blockIdx.x % 3;
    const int n0 = (blockIdx.x / 3) * 256;
    const int tid = threadIdx.x;
    const int lane = tid & 31, wid = tid >> 5;
    const int wm = wid & 3, wn = wid >> 2;

    float4 acc[2][4][2];
#pragma unroll
    for (int a = 0; a < 2; a++)
#pragma unroll
        for (int p = 0; p < 4; p++)
#pragma unroll
            for (int j = 0; j < 2; j++) acc[a][p][j] = make_float4(0.f, 0.f, 0.f, 0.f);

    const __nv_bfloat16* aH = (const __nv_bfloat16*)g_WH + (size_t)w * HD * CCH;
    const __nv_bfloat16* aL = (const __nv_bfloat16*)g_WL + (size_t)w * HD * CCH;
    const float* xb = x + (size_t)b * CCH * NPIX + n0;

    const int KT = CCH / 64;   // 8
    float st[16];

    // prologue: tile 0 (A via cp.async, B via 2-half register staging)
    k1_load_A(sbase, 0, aH, aL);
    k1_ldg_B(st, xb, 0, 0);
    k1_sts_B(sbase, st, 0);
    k1_ldg_B(st, xb, 0, 1);
    k1_sts_B(sbase, st, 1);

    for (int kt = 0; kt < KT; kt++) {
        asm volatile("cp.async.wait_group 0;" ::: "memory");
        __syncthreads();
        if (kt + 1 < KT) {
            k1_load_A(sbase + ((kt + 1) & 1) * K1BUF, (kt + 1) * 64, aH, aL);
            k1_ldg_B(st, xb, (kt + 1) * 64, 0);
        }
        uint32_t bufb = sbase + (kt & 1) * K1BUF;
        compute_tile_k1<4>(bufb, bufb + 2 * SLAB_A, 256 * 128, 8192, lane, wm, wn, acc);
        if (kt + 1 < KT) {
            uint32_t nb = sbase + ((kt + 1) & 1) * K1BUF;
            k1_sts_B(nb, st, 0);
            k1_ldg_B(st, xb, (kt + 1) * 64, 1);
            k1_sts_B(nb, st, 1);
        }
    }

#pragma unroll
    for (int mt = 0; mt < 2; mt++)
#pragma unroll
        for (int ntp = 0; ntp < 4; ntp++)
#pragma unroll
            for (int j = 0; j < 2; j++) {
                int r = wm * 32 + mt * 16 + (lane >> 2);
                int c = wn * 64 + ntp * 16 + j * 8 + (lane & 3) * 2;
                float4 v = acc[mt][ntp][j];
                if (w == 1) {
                    uint32_t* DH0 = g_BfH + ((size_t)b * HD + r) * (NPIX / 2) + (n0 + c) / 2;
                    uint32_t* DL0 = g_BfL + ((size_t)b * HD + r) * (NPIX / 2) + (n0 + c) / 2;
                    uint32_t* DH1 = DH0 + 8 * (NPIX / 2);
                    uint32_t* DL1 = DL0 + 8 * (NPIX / 2);
                    __nv_bfloat16 h0, l0, h1, l1;
                    bsplit(v.x, h0, l0); bsplit(v.y, h1, l1);
                    *DH0 = packpair(h0, h1); *DL0 = packpair(l0, l1);
                    bsplit(v.z, h0, l0); bsplit(v.w, h1, l1);
                    *DH1 = packpair(h0, h1); *DL1 = packpair(l0, l1);
                } else {
                    const int wlog = (w == 0) ? 0 : 1;
                    float* D = g_logits + (((size_t)wlog * BATCH + b) * HD + r) * NPIX + n0 + c;
                    *(float2*)D              = make_float2(v.x, v.y);
                    *(float2*)(D + 8 * NPIX) = make_float2(v.z, v.w);
                }
            }
}

// ---------------------------------------------------------------------------
// K2: row softmax with shuffle reductions
// ---------------------------------------------------------------------------
__global__ void __launch_bounds__(256) k_softmax() {
    int rid = blockIdx.x;                       // 0..4095
    int wlog = (rid < 2048) ? 0 : 1;
    int r = rid & 2047;                         // b*128 + h
    const float* p = g_logits + ((size_t)(wlog * 2048 + r)) * NPIX;
    int tid = threadIdx.x;
    const int lane = tid & 31, wrp = tid >> 5;
    __shared__ float wred[8];

    float4 v[4];
#pragma unroll
    for (int q = 0; q < 4; q++) v[q] = *(const float4*)(p + (q * 256 + tid) * 4);

    float m = v[0].x;
#pragma unroll
    for (int q = 0; q < 4; q++) {
        m = fmaxf(m, v[q].x); m = fmaxf(m, v[q].y);
        m = fmaxf(m, v[q].z); m = fmaxf(m, v[q].w);
    }
#pragma unroll
    for (int off = 16; off > 0; off >>= 1)
        m = fmaxf(m, __shfl_xor_sync(0xffffffffu, m, off));
    if (lane == 0) wred[wrp] = m;
    __syncthreads();
    float M = wred[0];
#pragma unroll
    for (int i = 1; i < 8; i++) M = fmaxf(M, wred[i]);
    __syncthreads();

    float ssum = 0.0f;
#pragma unroll
    for (int q = 0; q < 4; q++) {
        v[q].x = expf(v[q].x - M); ssum += v[q].x;
        v[q].y = expf(v[q].y - M); ssum += v[q].y;
        v[q].z = expf(v[q].z - M); ssum += v[q].z;
        v[q].w = expf(v[q].w - M); ssum += v[q].w;
    }
#pragma unroll
    for (int off = 16; off > 0; off >>= 1)
        ssum += __shfl_xor_sync(0xffffffffu, ssum, off);
    if (lane == 0) wred[wrp] = ssum;
    __syncthreads();
    float S = 0.0f;
#pragma unroll
    for (int i = 0; i < 8; i++) S += wred[i];
    float inv = 1.0f / S;

    uint32_t* AH = (wlog == 0 ? g_AmH : g_CsH) + (size_t)r * (NPIX / 2);
    uint32_t* AL = (wlog == 0 ? g_AmL : g_CsL) + (size_t)r * (NPIX / 2);
#pragma unroll
    for (int q = 0; q < 4; q++) {
        int n2 = (q * 256 + tid) * 2;
        float a0 = v[q].x * inv, a1 = v[q].y * inv;
        float a2 = v[q].z * inv, a3 = v[q].w * inv;
        __nv_bfloat16 h0, l0, h1, l1;
        bsplit(a0, h0, l0); bsplit(a1, h1, l1);
        AH[n2] = packpair(h0, h1); AL[n2] = packpair(l0, l1);
        bsplit(a2, h0, l0); bsplit(a3, h1, l1);
        AH[n2 + 1] = packpair(h0, h1); AL[n2 + 1] = packpair(l0, l1);
    }
}

// ---------------------------------------------------------------------------
// K3: G[b] += Bf[b] @ Am[b]^T over n (8-way k-split, CTA tile 128x128)
// ---------------------------------------------------------------------------
__global__ void __launch_bounds__(512) k3_gemm() {
    extern __shared__ uint32_t smem[];
    uint32_t sbase = smem_u32(smem);
    const int b = blockIdx.x, kb = blockIdx.y * 512;
    const int tid = threadIdx.x;
    const int lane = tid & 31, wid = tid >> 5;
    const int wm = wid & 3, wn = wid >> 2;

    float4 acc[2][2][2];
#pragma unroll
    for (int a = 0; a < 2; a++)
#pragma unroll
        for (int p = 0; p < 2; p++)
#pragma unroll
            for (int j = 0; j < 2; j++) acc[a][p][j] = make_float4(0.f, 0.f, 0.f, 0.f);

    const __nv_bfloat16* aH = (const __nv_bfloat16*)g_BfH + (size_t)b * HD * NPIX + kb;
    const __nv_bfloat16* aL = (const __nv_bfloat16*)g_BfL + (size_t)b * HD * NPIX + kb;
    const __nv_bfloat16* bH = (const __nv_bfloat16*)g_AmH + (size_t)b * HD * NPIX + kb;
    const __nv_bfloat16* bL = (const __nv_bfloat16*)g_AmL + (size_t)b * HD * NPIX + kb;

    run_gemm<128, false>(sbase, 8, aH, aL, NPIX, bH, bL, NPIX, acc);

    float* Gp = g_G + (size_t)b * HD * HD;
#pragma unroll
    for (int mt = 0; mt < 2; mt++)
#pragma unroll
        for (int ntp = 0; ntp < 2; ntp++)
#pragma unroll
            for (int j = 0; j < 2; j++) {
                int r = wm * 32 + mt * 16 + (lane >> 2);
                int c = wn * 32 + ntp * 16 + j * 8 + (lane & 3) * 2;
                float4 v = acc[mt][ntp][j];
                atomicAdd(&Gp[r * HD + c],           v.x);
                atomicAdd(&Gp[r * HD + c + 1],       v.y);
                atomicAdd(&Gp[(r + 8) * HD + c],     v.z);
                atomicAdd(&Gp[(r + 8) * HD + c + 1], v.w);
            }
}

// ---------------------------------------------------------------------------
// K4: M2 = (s .* wProj) @ G  -> bf16 hi/lo [b][c][g]
// ---------------------------------------------------------------------------
__global__ void __launch_bounds__(256) k_M2t(const float* __restrict__ wProj) {
    __shared__ float As[16][128];
    __shared__ float Bs[16][128];
    const int b  = blockIdx.x;
    const int c0 = blockIdx.y * 128;
    const float* Gp = g_G + (size_t)b * HD * HD;
    const int tid = threadIdx.x;
    const int tx = tid & 15, ty = tid >> 4;

    float acc[8][8];
#pragma unroll
    for (int i = 0; i < 8; i++)
#pragma unroll
        for (int j = 0; j < 8; j++) acc[i][j] = 0.0f;

    for (int k0 = 0; k0 < HD; k0 += 16) {
#pragma unroll
        for (int s = tid; s < 512; s += 256) {
            int row = s >> 2, kq = (s & 3) << 2;
            float4 v = *(const float4*)(wProj + (size_t)(c0 + row) * HD + k0 + kq);
            As[kq + 0][row] = v.x; As[kq + 1][row] = v.y;
            As[kq + 2][row] = v.z; As[kq + 3][row] = v.w;
            int kr = s >> 5, nq = (s & 31) << 2;
            *(float4*)&Bs[kr][nq] = *(const float4*)(Gp + (size_t)(k0 + kr) * HD + nq);
        }
        __syncthreads();
#pragma unroll
        for (int k = 0; k < 16; k++) {
            float a[8], bb[8];
            *(float4*)(a)      = *(const float4*)&As[k][ty * 8];
            *(float4*)(a + 4)  = *(const float4*)&As[k][ty * 8 + 4];
            *(float4*)(bb)     = *(const float4*)&Bs[k][tx * 8];
            *(float4*)(bb + 4) = *(const float4*)&Bs[k][tx * 8 + 4];
#pragma unroll
            for (int i = 0; i < 8; i++)
#pragma unroll
                for (int j = 0; j < 8; j++) acc[i][j] = fmaf(a[i], bb[j], acc[i][j]);
        }
        __syncthreads();
    }
#pragma unroll
    for (int i = 0; i < 8; i++) {
        int c = c0 + ty * 8 + i;
        float sc = g_s[c];
        uint32_t* DH = g_M2H + ((size_t)b * CCH + c) * (HD / 2) + tx * 4;
        uint32_t* DL = g_M2L + ((size_t)b * CCH + c) * (HD / 2) + tx * 4;
#pragma unroll
        for (int j = 0; j < 4; j++) {
            float f0 = sc * acc[i][2 * j], f1 = sc * acc[i][2 * j + 1];
            __nv_bfloat16 h0, l0, h1, l1;
            bsplit(f0, h0, l0); bsplit(f1, h1, l1);
            DH[j] = packpair(h0, h1);
            DL[j] = packpair(l0, l1);
        }
    }
}

// ---------------------------------------------------------------------------
// K5: out[b] = M2[b] @ Cs[b] + t.  Resident Cs, 8 pipelined c/k steps.
// ---------------------------------------------------------------------------
static constexpr int K5_CHUNK = 16384;
static constexpr int K5_CS_L  = 32768;
static constexpr int K5_A0    = 65536;
static constexpr int K5_ABUF  = 32768;
static constexpr int K5_SMEM  = 65536 + 2 * 32768;   // 128 KB

__device__ __forceinline__ void k5_loadA(uint32_t sbase, int b, int s_idx) {
    const int tid = threadIdx.x;
    const int c0 = (s_idx >> 1) * 128, ks = (s_idx & 1) * 64;
    uint32_t abuf = sbase + K5_A0 + (uint32_t)(s_idx & 1) * K5_ABUF;
    const __nv_bfloat16* mH = (const __nv_bfloat16*)g_M2H + ((size_t)b * CCH + c0) * HD + ks;
    const __nv_bfloat16* mL = (const __nv_bfloat16*)g_M2L + ((size_t)b * CCH + c0) * HD + ks;
#pragma unroll
    for (int i = 0; i < 4; i++) {
        int g = tid + i * 512;
        int half = g >> 10, g3 = g & 1023;
        int row = g3 >> 3, gran = g3 & 7;
        const __nv_bfloat16* s = half ? mL : mH;
        cp16(abuf + (uint32_t)half * 16384 + SW128(row * 128 + gran * 16),
             s + (size_t)row * HD + gran * 8);
    }
    asm volatile("cp.async.commit_group;" ::: "memory");
}

__global__ void __launch_bounds__(512) k5_gemm(float* __restrict__ out) {
    extern __shared__ uint32_t smem[];
    uint32_t sbase = smem_u32(smem);
    const int b = blockIdx.z;
    const int n0 = blockIdx.x * 128;
    const int tid = threadIdx.x;
    const int lane = tid & 31, wid = tid >> 5;
    const int wm = wid & 3, wn = wid >> 2;

    {
        const __nv_bfloat16* csH = (const __nv_bfloat16*)g_CsH + (size_t)b * HD * NPIX + n0;
        const __nv_bfloat16* csL = (const __nv_bfloat16*)g_CsL + (size_t)b * HD * NPIX + n0;
#pragma unroll
        for (int i = 0; i < 8; i++) {
            int g = tid + i * 512;
            int half = g >> 11, g3 = g & 2047;
            int krow = g3 >> 4, g16 = g3 & 15;
            int chunk = g16 >> 3, col16 = g16 & 7;
            const __nv_bfloat16* s = half ? csL : csH;
            cp16(sbase + (uint32_t)half * K5_CS_L + chunk * K5_CHUNK +
                     SW128(krow * 128 + col16 * 16),
                 s + (size_t)krow * NPIX + g16 * 8);
        }
    }
    k5_loadA(sbase, b, 0);

    float4 acc[2][2][2];
#pragma unroll
    for (int a = 0; a < 2; a++)
#pragma unroll
        for (int p = 0; p < 2; p++)
#pragma unroll
            for (int j = 0; j < 2; j++) acc[a][p][j] = make_float4(0.f, 0.f, 0.f, 0.f);

    for (int s = 0; s < 8; s++) {
        const int c0 = s >> 1, ksub = s & 1;
        asm volatile("cp.async.wait_group 0;" ::: "memory");
        __syncthreads();
        if (s + 1 < 8) k5_loadA(sbase, b, s + 1);

        const uint32_t abuf = sbase + K5_A0 + (uint32_t)(s & 1) * K5_ABUF;
        compute_tile2<2, true>(abuf, 16384, sbase, K5_CS_L,
                               K5_CHUNK, ksub * 64, lane, wm, wn, acc);

        if (ksub == 1) {
#pragma unroll
            for (int mt = 0; mt < 2; mt++)
#pragma unroll
                for (int ntp = 0; ntp < 2; ntp++)
#pragma unroll
                    for (int j = 0; j < 2; j++) {
                        int r = wm * 32 + mt * 16 + (lane >> 2);
                        int c = wn * 32 + ntp * 16 + j * 8 + (lane & 3) * 2;
                        float4 v = acc[mt][ntp][j];
                        float t0 = g_t[c0 * 128 + r];
                        float t1 = g_t[c0 * 128 + r + 8];
                        float* D = out + ((size_t)b * CCH + c0 * 128 + r) * NPIX + n0 + c;
                        *(float2*)D              = make_float2(v.x + t0, v.y + t0);
                        *(float2*)(D + 8 * NPIX) = make_float2(v.z + t1, v.w + t1);
                        acc[mt][ntp][j] = make_float4(0.f, 0.f, 0.f, 0.f);
                    }
        }
    }
}

// ---------------------------------------------------------------------------
extern "C" void kernel_launch(void* const* d_in, const int* in_sizes, int n_in,
                              void* d_out, int out_size) {
    const float* x     = (const float*)d_in[0];
    const float* wA    = (const float*)d_in[1];
    const float* wB    = (const float*)d_in[2];
    const float* wC    = (const float*)d_in[3];
    const float* wProj = (const float*)d_in[4];
    const float* gamma = (const float*)d_in[5];
    const float* beta  = (const float*)d_in[6];
    const float* mean  = (const float*)d_in[7];
    const float* var   = (const float*)d_in[8];
    float* out = (float*)d_out;

    const int smem_128 = 2 * GeomT<128>::BUF;   // 128KB
    const int smem_k1  = 2 * K1BUF;             // 192KB
    cudaFuncSetAttribute(k1_gemm, cudaFuncAttributeMaxDynamicSharedMemorySize, smem_k1);
    cudaFuncSetAttribute(k3_gemm, cudaFuncAttributeMaxDynamicSharedMemorySize, smem_128);
    cudaFuncSetAttribute(k5_gemm, cudaFuncAttributeMaxDynamicSharedMemorySize, K5_SMEM);

    k_prep<<<1024, 256>>>(gamma, beta, mean, var, wA, wB, wC);
    k1_gemm<<<dim3(48, 1, BATCH), 512, smem_k1>>>(x);
    k_softmax<<<4096, 256>>>();
    k3_gemm<<<dim3(BATCH, 8), 512, smem_128>>>();
    k_M2t<<<dim3(BATCH, CCH / 128), 256>>>(wProj);
    k5_gemm<<<dim3(32, 1, BATCH), 512, K5_SMEM>>>(out);
}

// round 14
// speedup vs baseline: 1.0865x; 1.0865x over previous
#include <cuda_runtime.h>
#include <cuda_bf16.h>
#include <cstdint>

static constexpr int BATCH = 16;
static constexpr int CCH   = 512;
static constexpr int NPIX  = 4096;
static constexpr int HD    = 128;

// fp32 logits (pre-softmax) for A (idx 0) and C (idx 1)
__device__ float g_logits[(size_t)2 * BATCH * HD * NPIX];
// bf16 hi/lo operand stores (as u32 pair arrays)
__device__ uint32_t g_WH[3 * HD * CCH / 2],        g_WL[3 * HD * CCH / 2];
__device__ uint32_t g_BfH[(size_t)BATCH * HD * NPIX / 2],  g_BfL[(size_t)BATCH * HD * NPIX / 2];
__device__ uint32_t g_AmH[(size_t)BATCH * HD * NPIX / 2],  g_AmL[(size_t)BATCH * HD * NPIX / 2];
__device__ uint32_t g_CsH[(size_t)BATCH * HD * NPIX / 2],  g_CsL[(size_t)BATCH * HD * NPIX / 2];
__device__ uint32_t g_M2H[BATCH * CCH * HD / 2],   g_M2L[BATCH * CCH * HD / 2];
__device__ float g_G[BATCH * HD * HD];
__device__ float g_s[CCH];
__device__ float g_t[CCH];

// ---------------------------------------------------------------------------
__device__ __forceinline__ uint32_t smem_u32(const void* p) {
    uint32_t a;
    asm("{ .reg .u64 t; cvta.to.shared.u64 t, %1; cvt.u32.u64 %0, t; }" : "=r"(a) : "l"(p));
    return a;
}
__device__ __forceinline__ void bsplit(float x, __nv_bfloat16& h, __nv_bfloat16& l) {
    h = __float2bfloat16_rn(x);
    l = __float2bfloat16_rn(x - __bfloat162float(h));
}
__device__ __forceinline__ uint32_t packpair(__nv_bfloat16 a, __nv_bfloat16 b) {
    uint16_t au = *(uint16_t*)&a, bu = *(uint16_t*)&b;
    return (uint32_t)au | ((uint32_t)bu << 16);
}
__device__ __forceinline__ void cp16(uint32_t dst, const void* src) {
    asm volatile("cp.async.cg.shared.global [%0], [%1], 16;" :: "r"(dst), "l"(src));
}
#define SW128(off) ((off) ^ (((off) >> 3) & 0x70))

__device__ __forceinline__ void ldsm4(uint32_t (&r)[4], uint32_t addr) {
    asm volatile("ldmatrix.sync.aligned.m8n8.x4.shared.b16 {%0,%1,%2,%3}, [%4];"
                 : "=r"(r[0]), "=r"(r[1]), "=r"(r[2]), "=r"(r[3]) : "r"(addr));
}
__device__ __forceinline__ void ldsm4t(uint32_t (&r)[4], uint32_t addr) {
    asm volatile("ldmatrix.sync.aligned.m8n8.x4.trans.shared.b16 {%0,%1,%2,%3}, [%4];"
                 : "=r"(r[0]), "=r"(r[1]), "=r"(r[2]), "=r"(r[3]) : "r"(addr));
}
__device__ __forceinline__ void mma16(float4& d, const uint32_t* a, uint32_t b0, uint32_t b1) {
    asm volatile("mma.sync.aligned.m16n8k16.row.col.f32.bf16.bf16.f32 "
                 "{%0,%1,%2,%3},{%4,%5,%6,%7},{%8,%9},{%0,%1,%2,%3};"
                 : "+f"(d.x), "+f"(d.y), "+f"(d.z), "+f"(d.w)
                 : "r"(a[0]), "r"(a[1]), "r"(a[2]), "r"(a[3]), "r"(b0), "r"(b1));
}

// ---------------------------------------------------------------------------
// generic compute core: NP n16-groups per warp, BK=64
// ---------------------------------------------------------------------------
static constexpr int SLAB_A = 16384;   // 128 rows x 128B

template<int NP, bool TRB>
__device__ __forceinline__ void compute_tile2(
    uint32_t abase, uint32_t ahalfoff,
    uint32_t bbase, uint32_t bhalfoff, int bchstride, int browoff,
    int lane, int wm, int wn, float4 (&acc)[2][NP][2]) {
    const int rl = lane & 15, gh = lane >> 4;
    constexpr int WN = NP * 16;

    uint32_t aH[2][2][4], aL[2][2][4];
    uint32_t bh[2][4], bl[2][4];

    auto loadA = [&](int ks, int buf) {
#pragma unroll
        for (int mt = 0; mt < 2; mt++) {
            uint32_t ar = abase + SW128((wm * 32 + mt * 16 + rl) * 128 + (ks * 2 + gh) * 16);
            ldsm4(aH[buf][mt], ar);
            ldsm4(aL[buf][mt], ar + ahalfoff);
        }
    };
    auto loadB = [&](int ks, int ntp, int buf) {
        if (!TRB) {
            uint32_t br = bbase + SW128((wn * WN + ntp * 16 + rl) * 128 + (ks * 2 + gh) * 16);
            ldsm4(bh[buf], br);
            ldsm4(bl[buf], br + bhalfoff);
        } else {
            int n = wn * WN + ntp * 16 + gh * 8;
            int chunk = n >> 6, col16 = (n & 63) >> 3;
            uint32_t br = bbase + chunk * bchstride +
                          SW128((browoff + ks * 16 + rl) * 128 + col16 * 16);
            ldsm4t(bh[buf], br);
            ldsm4t(bl[buf], br + bhalfoff);
        }
    };

    loadA(0, 0);
    loadB(0, 0, 0);
#pragma unroll
    for (int ks = 0; ks < 4; ks++) {
        const int ab = ks & 1;
#pragma unroll
        for (int ntp = 0; ntp < NP; ntp++) {
            const int bb = (ks * NP + ntp) & 1;
            if (ntp + 1 < NP) {
                loadB(ks, ntp + 1, (ks * NP + ntp + 1) & 1);
            } else if (ks + 1 < 4) {
                loadA(ks + 1, (ks + 1) & 1);
                loadB(ks + 1, 0, ((ks + 1) * NP) & 1);
            }
            uint32_t b0h[2], b1h[2], b0l[2], b1l[2];
#pragma unroll
            for (int j = 0; j < 2; j++) {
                b0h[j] = TRB ? bh[bb][2 * j]     : bh[bb][j];
                b1h[j] = TRB ? bh[bb][2 * j + 1] : bh[bb][j + 2];
                b0l[j] = TRB ? bl[bb][2 * j]     : bl[bb][j];
                b1l[j] = TRB ? bl[bb][2 * j + 1] : bl[bb][j + 2];
            }
#pragma unroll
            for (int j = 0; j < 2; j++)
#pragma unroll
                for (int mt = 0; mt < 2; mt++)
                    mma16(acc[mt][ntp][j], aH[ab][mt], b0h[j], b1h[j]);
#pragma unroll
            for (int j = 0; j < 2; j++)
#pragma unroll
                for (int mt = 0; mt < 2; mt++)
                    mma16(acc[mt][ntp][j], aH[ab][mt], b0l[j], b1l[j]);
#pragma unroll
            for (int j = 0; j < 2; j++)
#pragma unroll
                for (int mt = 0; mt < 2; mt++)
                    mma16(acc[mt][ntp][j], aL[ab][mt], b0h[j], b1h[j]);
        }
    }
}

// ---------------------------------------------------------------------------
// smem tile loader for k3 (NN=128, k-major B)
// ---------------------------------------------------------------------------
template<int NN>
struct GeomT {
    static constexpr int WN    = NN / 4;
    static constexpr int NP16  = WN / 16;
    static constexpr int BUF   = 2 * SLAB_A + 2 * NN * 128;
    static constexpr int ITER  = (256 + 2 * NN) / 64;
};

template<int NN, bool TRB>
__device__ __forceinline__ void load_tile(uint32_t bufb, int kofs,
                                          const __nv_bfloat16* aH, const __nv_bfloat16* aL, int sA,
                                          const __nv_bfloat16* bH, const __nv_bfloat16* bL, int sB) {
    const int tid = threadIdx.x;
#pragma unroll
    for (int i = 0; i < GeomT<NN>::ITER; i++) {
        int g = tid + i * 512;
        if (g < 2048) {
            int row_lin = g >> 3, gran = g & 7;
            const __nv_bfloat16* s = (row_lin < 128) ? aH : aL;
            int row = row_lin & 127;
            uint32_t slaboff = (row_lin < 128) ? 0u : (uint32_t)SLAB_A;
            cp16(bufb + slaboff + SW128(row * 128 + gran * 16),
                 s + (size_t)row * sA + kofs + gran * 8);
        } else {
            int g2 = g - 2048;
            int half = g2 / (NN * 8);
            int g3 = g2 % (NN * 8);
            const __nv_bfloat16* s = half ? bL : bH;
            uint32_t slaboff = 2 * SLAB_A + (uint32_t)half * NN * 128;
            if (!TRB) {
                int row = g3 >> 3, gran = g3 & 7;
                cp16(bufb + slaboff + SW128(row * 128 + gran * 16),
                     s + (size_t)row * sB + kofs + gran * 8);
            } else {
                int krow = g3 >> 5, g32 = g3 & 31;
                int chunk = g32 >> 3, col16 = g32 & 7;
                cp16(bufb + slaboff + chunk * 8192 + SW128(krow * 128 + col16 * 16),
                     s + (size_t)(kofs + krow) * sB + g32 * 8);
            }
        }
    }
    asm volatile("cp.async.commit_group;" ::: "memory");
}

template<int NN, bool TRB>
__device__ __forceinline__ void run_gemm(uint32_t sbase, int KT,
                                         const __nv_bfloat16* aH, const __nv_bfloat16* aL, int sA,
                                         const __nv_bfloat16* bH, const __nv_bfloat16* bL, int sB,
                                         float4 (&acc)[2][GeomT<NN>::NP16][2]) {
    const int tid = threadIdx.x;
    const int lane = tid & 31, wid = tid >> 5;
    const int wm = wid & 3, wn = wid >> 2;

    load_tile<NN, TRB>(sbase, 0, aH, aL, sA, bH, bL, sB);
    for (int kt = 0; kt < KT; kt++) {
        asm volatile("cp.async.wait_group 0;" ::: "memory");
        __syncthreads();
        if (kt + 1 < KT)
            load_tile<NN, TRB>(sbase + ((kt + 1) & 1) * GeomT<NN>::BUF, (kt + 1) * 64,
                               aH, aL, sA, bH, bL, sB);
        uint32_t bufb = sbase + (kt & 1) * GeomT<NN>::BUF;
        compute_tile2<GeomT<NN>::NP16, TRB>(bufb, SLAB_A,
                                            bufb + 2 * SLAB_A, (uint32_t)(NN * 128),
                                            8192, 0, lane, wm, wn, acc);
    }
}

// ---------------------------------------------------------------------------
// prep
// ---------------------------------------------------------------------------
__global__ void __launch_bounds__(256) k_prep(const float* __restrict__ gamma,
                                              const float* __restrict__ beta,
                                              const float* __restrict__ mean,
                                              const float* __restrict__ var,
                                              const float* __restrict__ wA,
                                              const float* __restrict__ wB,
                                              const float* __restrict__ wC) {
    int idx = blockIdx.x * 256 + threadIdx.x;
    if (idx < BATCH * HD * HD) g_G[idx] = 0.0f;
    if (idx < CCH) {
        float inv = rsqrtf(var[idx] + 1e-5f);
        float sc  = inv * gamma[idx];
        g_s[idx] = sc;
        g_t[idx] = beta[idx] - mean[idx] * sc;
    }
    if (idx < 3 * HD * CCH / 2) {
        const float* src = (idx < 32768) ? wA : (idx < 65536) ? wB : wC;
        int lp = idx & 32767;
        float f0 = src[2 * lp], f1 = src[2 * lp + 1];
        __nv_bfloat16 h0, l0, h1, l1;
        bsplit(f0, h0, l0); bsplit(f1, h1, l1);
        g_WH[idx] = packpair(h0, h1);
        g_WL[idx] = packpair(l0, l1);
    }
}

// ---------------------------------------------------------------------------
// K1: logits = W[w] @ x[b], NN=128, direct-x fused split (R12 geometry),
// PERSISTENT grid-stride over the 1536 tiles (1520 CTAs = 10 full waves).
// ---------------------------------------------------------------------------
static constexpr int K1BUF   = 2 * SLAB_A + 2 * 128 * 128;   // 64 KB per stage
static constexpr int K1_TILES = 96 * BATCH;                  // 1536
static constexpr int K1_GRID  = 1520;                        // 152 x 10

__device__ __forceinline__ void k1_load_A(uint32_t bufb, int kofs,
                                          const __nv_bfloat16* aH, const __nv_bfloat16* aL) {
    const int tid = threadIdx.x;
#pragma unroll
    for (int i = 0; i < 4; i++) {
        int g = tid + i * 512;
        int row_lin = g >> 3, gran = g & 7;
        const __nv_bfloat16* s = (row_lin < 128) ? aH : aL;
        int row = row_lin & 127;
        uint32_t slaboff = (row_lin < 128) ? 0u : (uint32_t)SLAB_A;
        cp16(bufb + slaboff + SW128(row * 128 + gran * 16),
             s + (size_t)row * CCH + kofs + gran * 8);
    }
    asm volatile("cp.async.commit_group;" ::: "memory");
}

__device__ __forceinline__ void k1_ldg_B(float (&st)[16], const float* xb, int kofs) {
    const int tid = threadIdx.x;
#pragma unroll
    for (int i = 0; i < 4; i++) {
        int idx = tid + i * 512;
        int krow = idx >> 5, ng4 = idx & 31;
        const float* p = xb + (size_t)(kofs + krow) * NPIX + ng4 * 4;
        asm volatile("ld.global.nc.v4.f32 {%0,%1,%2,%3}, [%4];"
                     : "=f"(st[4 * i]), "=f"(st[4 * i + 1]),
                       "=f"(st[4 * i + 2]), "=f"(st[4 * i + 3]) : "l"(p));
    }
}

__device__ __forceinline__ void k1_sts_B(uint32_t bufb, const float (&st)[16]) {
    const int tid = threadIdx.x;
    const uint32_t bsb = bufb + 2 * SLAB_A;
#pragma unroll
    for (int i = 0; i < 4; i++) {
        int idx = tid + i * 512;
        int krow = idx >> 5, ng4 = idx & 31;
        int n = ng4 * 4;
        int chunk = n >> 6;
        uint32_t off = bsb + chunk * 8192 + SW128((uint32_t)(krow * 128 + (n & 63) * 2));
        __nv_bfloat16 h0, l0, h1, l1, h2, l2, h3, l3;
        bsplit(st[4 * i],     h0, l0);
        bsplit(st[4 * i + 1], h1, l1);
        bsplit(st[4 * i + 2], h2, l2);
        bsplit(st[4 * i + 3], h3, l3);
        uint32_t hi01 = packpair(h0, h1), hi23 = packpair(h2, h3);
        uint32_t lo01 = packpair(l0, l1), lo23 = packpair(l2, l3);
        asm volatile("st.shared.v2.u32 [%0], {%1,%2};"
                     :: "r"(off), "r"(hi01), "r"(hi23) : "memory");
        asm volatile("st.shared.v2.u32 [%0], {%1,%2};"
                     :: "r"(off + 128 * 128), "r"(lo01), "r"(lo23) : "memory");
    }
}

__global__ void __launch_bounds__(512) k1_gemm(const float* __restrict__ x) {
    extern __shared__ uint32_t smem[];
    uint32_t sbase = smem_u32(smem);
    const int tid = threadIdx.x;
    const int lane = tid & 31, wid = tid >> 5;
    const int wm = wid & 3, wn = wid >> 2;

    for (int t = blockIdx.x; t < K1_TILES; t += K1_GRID) {
        const int b  = t / 96;
        const int r96 = t % 96;
        const int w  = r96 % 3;
        const int n0 = (r96 / 3) * 128;

        float4 acc[2][2][2];
#pragma unroll
        for (int a = 0; a < 2; a++)
#pragma unroll
            for (int p = 0; p < 2; p++)
#pragma unroll
                for (int j = 0; j < 2; j++) acc[a][p][j] = make_float4(0.f, 0.f, 0.f, 0.f);

        const __nv_bfloat16* aH = (const __nv_bfloat16*)g_WH + (size_t)w * HD * CCH;
        const __nv_bfloat16* aL = (const __nv_bfloat16*)g_WL + (size_t)w * HD * CCH;
        const float* xb = x + (size_t)b * CCH * NPIX + n0;

        const int KT = CCH / 64;   // 8
        float st[16];

        k1_ldg_B(st, xb, 0);
        k1_load_A(sbase, 0, aH, aL);
        k1_sts_B(sbase, st);

        for (int kt = 0; kt < KT; kt++) {
            asm volatile("cp.async.wait_group 0;" ::: "memory");
            __syncthreads();
            if (kt + 1 < KT) {
                k1_ldg_B(st, xb, (kt + 1) * 64);
                k1_load_A(sbase + ((kt + 1) & 1) * K1BUF, (kt + 1) * 64, aH, aL);
            }
            uint32_t bufb = sbase + (kt & 1) * K1BUF;
            compute_tile2<2, true>(bufb, SLAB_A, bufb + 2 * SLAB_A, 128 * 128,
                                   8192, 0, lane, wm, wn, acc);
            if (kt + 1 < KT)
                k1_sts_B(sbase + ((kt + 1) & 1) * K1BUF, st);
        }

#pragma unroll
        for (int mt = 0; mt < 2; mt++)
#pragma unroll
            for (int ntp = 0; ntp < 2; ntp++)
#pragma unroll
                for (int j = 0; j < 2; j++) {
                    int r = wm * 32 + mt * 16 + (lane >> 2);
                    int c = wn * 32 + ntp * 16 + j * 8 + (lane & 3) * 2;
                    float4 v = acc[mt][ntp][j];
                    if (w == 1) {
                        uint32_t* DH0 = g_BfH + ((size_t)b * HD + r) * (NPIX / 2) + (n0 + c) / 2;
                        uint32_t* DL0 = g_BfL + ((size_t)b * HD + r) * (NPIX / 2) + (n0 + c) / 2;
                        uint32_t* DH1 = DH0 + 8 * (NPIX / 2);
                        uint32_t* DL1 = DL0 + 8 * (NPIX / 2);
                        __nv_bfloat16 h0, l0, h1, l1;
                        bsplit(v.x, h0, l0); bsplit(v.y, h1, l1);
                        *DH0 = packpair(h0, h1); *DL0 = packpair(l0, l1);
                        bsplit(v.z, h0, l0); bsplit(v.w, h1, l1);
                        *DH1 = packpair(h0, h1); *DL1 = packpair(l0, l1);
                    } else {
                        const int wlog = (w == 0) ? 0 : 1;
                        float* D = g_logits + (((size_t)wlog * BATCH + b) * HD + r) * NPIX + n0 + c;
                        *(float2*)D              = make_float2(v.x, v.y);
                        *(float2*)(D + 8 * NPIX) = make_float2(v.z, v.w);
                    }
                }
        __syncthreads();   // all stores done before next tile overwrites smem
    }
}

// ---------------------------------------------------------------------------
// K2: row softmax with shuffle reductions
// ---------------------------------------------------------------------------
__global__ void __launch_bounds__(256) k_softmax() {
    int rid = blockIdx.x;                       // 0..4095
    int wlog = (rid < 2048) ? 0 : 1;
    int r = rid & 2047;                         // b*128 + h
    const float* p = g_logits + ((size_t)(wlog * 2048 + r)) * NPIX;
    int tid = threadIdx.x;
    const int lane = tid & 31, wrp = tid >> 5;
    __shared__ float wred[8];

    float4 v[4];
#pragma unroll
    for (int q = 0; q < 4; q++) v[q] = *(const float4*)(p + (q * 256 + tid) * 4);

    float m = v[0].x;
#pragma unroll
    for (int q = 0; q < 4; q++) {
        m = fmaxf(m, v[q].x); m = fmaxf(m, v[q].y);
        m = fmaxf(m, v[q].z); m = fmaxf(m, v[q].w);
    }
#pragma unroll
    for (int off = 16; off > 0; off >>= 1)
        m = fmaxf(m, __shfl_xor_sync(0xffffffffu, m, off));
    if (lane == 0) wred[wrp] = m;
    __syncthreads();
    float M = wred[0];
#pragma unroll
    for (int i = 1; i < 8; i++) M = fmaxf(M, wred[i]);
    __syncthreads();

    float ssum = 0.0f;
#pragma unroll
    for (int q = 0; q < 4; q++) {
        v[q].x = expf(v[q].x - M); ssum += v[q].x;
        v[q].y = expf(v[q].y - M); ssum += v[q].y;
        v[q].z = expf(v[q].z - M); ssum += v[q].z;
        v[q].w = expf(v[q].w - M); ssum += v[q].w;
    }
#pragma unroll
    for (int off = 16; off > 0; off >>= 1)
        ssum += __shfl_xor_sync(0xffffffffu, ssum, off);
    if (lane == 0) wred[wrp] = ssum;
    __syncthreads();
    float S = 0.0f;
#pragma unroll
    for (int i = 0; i < 8; i++) S += wred[i];
    float inv = 1.0f / S;

    uint32_t* AH = (wlog == 0 ? g_AmH : g_CsH) + (size_t)r * (NPIX / 2);
    uint32_t* AL = (wlog == 0 ? g_AmL : g_CsL) + (size_t)r * (NPIX / 2);
#pragma unroll
    for (int q = 0; q < 4; q++) {
        int n2 = (q * 256 + tid) * 2;
        float a0 = v[q].x * inv, a1 = v[q].y * inv;
        float a2 = v[q].z * inv, a3 = v[q].w * inv;
        __nv_bfloat16 h0, l0, h1, l1;
        bsplit(a0, h0, l0); bsplit(a1, h1, l1);
        AH[n2] = packpair(h0, h1); AL[n2] = packpair(l0, l1);
        bsplit(a2, h0, l0); bsplit(a3, h1, l1);
        AH[n2 + 1] = packpair(h0, h1); AL[n2 + 1] = packpair(l0, l1);
    }
}

// ---------------------------------------------------------------------------
// K3: G[b] += Bf[b] @ Am[b]^T over n (8-way k-split, CTA tile 128x128)
// ---------------------------------------------------------------------------
__global__ void __launch_bounds__(512) k3_gemm() {
    extern __shared__ uint32_t smem[];
    uint32_t sbase = smem_u32(smem);
    const int b = blockIdx.x, kb = blockIdx.y * 512;
    const int tid = threadIdx.x;
    const int lane = tid & 31, wid = tid >> 5;
    const int wm = wid & 3, wn = wid >> 2;

    float4 acc[2][2][2];
#pragma unroll
    for (int a = 0; a < 2; a++)
#pragma unroll
        for (int p = 0; p < 2; p++)
#pragma unroll
            for (int j = 0; j < 2; j++) acc[a][p][j] = make_float4(0.f, 0.f, 0.f, 0.f);

    const __nv_bfloat16* aH = (const __nv_bfloat16*)g_BfH + (size_t)b * HD * NPIX + kb;
    const __nv_bfloat16* aL = (const __nv_bfloat16*)g_BfL + (size_t)b * HD * NPIX + kb;
    const __nv_bfloat16* bH = (const __nv_bfloat16*)g_AmH + (size_t)b * HD * NPIX + kb;
    const __nv_bfloat16* bL = (const __nv_bfloat16*)g_AmL + (size_t)b * HD * NPIX + kb;

    run_gemm<128, false>(sbase, 8, aH, aL, NPIX, bH, bL, NPIX, acc);

    float* Gp = g_G + (size_t)b * HD * HD;
#pragma unroll
    for (int mt = 0; mt < 2; mt++)
#pragma unroll
        for (int ntp = 0; ntp < 2; ntp++)
#pragma unroll
            for (int j = 0; j < 2; j++) {
                int r = wm * 32 + mt * 16 + (lane >> 2);
                int c = wn * 32 + ntp * 16 + j * 8 + (lane & 3) * 2;
                float4 v = acc[mt][ntp][j];
                atomicAdd(&Gp[r * HD + c],           v.x);
                atomicAdd(&Gp[r * HD + c + 1],       v.y);
                atomicAdd(&Gp[(r + 8) * HD + c],     v.z);
                atomicAdd(&Gp[(r + 8) * HD + c + 1], v.w);
            }
}

// ---------------------------------------------------------------------------
// K4: M2 = (s .* wProj) @ G  -> bf16 hi/lo [b][c][g]
// ---------------------------------------------------------------------------
__global__ void __launch_bounds__(256) k_M2t(const float* __restrict__ wProj) {
    __shared__ float As[16][128];
    __shared__ float Bs[16][128];
    const int b  = blockIdx.x;
    const int c0 = blockIdx.y * 128;
    const float* Gp = g_G + (size_t)b * HD * HD;
    const int tid = threadIdx.x;
    const int tx = tid & 15, ty = tid >> 4;

    float acc[8][8];
#pragma unroll
    for (int i = 0; i < 8; i++)
#pragma unroll
        for (int j = 0; j < 8; j++) acc[i][j] = 0.0f;

    for (int k0 = 0; k0 < HD; k0 += 16) {
#pragma unroll
        for (int s = tid; s < 512; s += 256) {
            int row = s >> 2, kq = (s & 3) << 2;
            float4 v = *(const float4*)(wProj + (size_t)(c0 + row) * HD + k0 + kq);
            As[kq + 0][row] = v.x; As[kq + 1][row] = v.y;
            As[kq + 2][row] = v.z; As[kq + 3][row] = v.w;
            int kr = s >> 5, nq = (s & 31) << 2;
            *(float4*)&Bs[kr][nq] = *(const float4*)(Gp + (size_t)(k0 + kr) * HD + nq);
        }
        __syncthreads();
#pragma unroll
        for (int k = 0; k < 16; k++) {
            float a[8], bb[8];
            *(float4*)(a)      = *(const float4*)&As[k][ty * 8];
            *(float4*)(a + 4)  = *(const float4*)&As[k][ty * 8 + 4];
            *(float4*)(bb)     = *(const float4*)&Bs[k][tx * 8];
            *(float4*)(bb + 4) = *(const float4*)&Bs[k][tx * 8 + 4];
#pragma unroll
            for (int i = 0; i < 8; i++)
#pragma unroll
                for (int j = 0; j < 8; j++) acc[i][j] = fmaf(a[i], bb[j], acc[i][j]);
        }
        __syncthreads();
    }
#pragma unroll
    for (int i = 0; i < 8; i++) {
        int c = c0 + ty * 8 + i;
        float sc = g_s[c];
        uint32_t* DH = g_M2H + ((size_t)b * CCH + c) * (HD / 2) + tx * 4;
        uint32_t* DL = g_M2L + ((size_t)b * CCH + c) * (HD / 2) + tx * 4;
#pragma unroll
        for (int j = 0; j < 4; j++) {
            float f0 = sc * acc[i][2 * j], f1 = sc * acc[i][2 * j + 1];
            __nv_bfloat16 h0, l0, h1, l1;
            bsplit(f0, h0, l0); bsplit(f1, h1, l1);
            DH[j] = packpair(h0, h1);
            DL[j] = packpair(l0, l1);
        }
    }
}

// ---------------------------------------------------------------------------
// K5: out[b] = M2[b] @ Cs[b] + t.  Resident Cs, 8 pipelined c/k steps,
// PERSISTENT grid-stride over the 512 tiles (456 CTAs = 3 full waves).
// ---------------------------------------------------------------------------
static constexpr int K5_CHUNK = 16384;
static constexpr int K5_CS_L  = 32768;
static constexpr int K5_A0    = 65536;
static constexpr int K5_ABUF  = 32768;
static constexpr int K5_SMEM  = 65536 + 2 * 32768;   // 128 KB
static constexpr int K5_TILES = 32 * BATCH;          // 512
static constexpr int K5_GRID  = 456;                 // 152 x 3

__device__ __forceinline__ void k5_loadA(uint32_t sbase, int b, int s_idx) {
    const int tid = threadIdx.x;
    const int c0 = (s_idx >> 1) * 128, ks = (s_idx & 1) * 64;
    uint32_t abuf = sbase + K5_A0 + (uint32_t)(s_idx & 1) * K5_ABUF;
    const __nv_bfloat16* mH = (const __nv_bfloat16*)g_M2H + ((size_t)b * CCH + c0) * HD + ks;
    const __nv_bfloat16* mL = (const __nv_bfloat16*)g_M2L + ((size_t)b * CCH + c0) * HD + ks;
#pragma unroll
    for (int i = 0; i < 4; i++) {
        int g = tid + i * 512;
        int half = g >> 10, g3 = g & 1023;
        int row = g3 >> 3, gran = g3 & 7;
        const __nv_bfloat16* s = half ? mL : mH;
        cp16(abuf + (uint32_t)half * 16384 + SW128(row * 128 + gran * 16),
             s + (size_t)row * HD + gran * 8);
    }
    asm volatile("cp.async.commit_group;" ::: "memory");
}

__global__ void __launch_bounds__(512) k5_gemm(float* __restrict__ out) {
    extern __shared__ uint32_t smem[];
    uint32_t sbase = smem_u32(smem);
    const int tid = threadIdx.x;
    const int lane = tid & 31, wid = tid >> 5;
    const int wm = wid & 3, wn = wid >> 2;

    for (int t = blockIdx.x; t < K5_TILES; t += K5_GRID) {
        const int b  = t >> 5;
        const int n0 = (t & 31) * 128;

        {
            const __nv_bfloat16* csH = (const __nv_bfloat16*)g_CsH + (size_t)b * HD * NPIX + n0;
            const __nv_bfloat16* csL = (const __nv_bfloat16*)g_CsL + (size_t)b * HD * NPIX + n0;
#pragma unroll
            for (int i = 0; i < 8; i++) {
                int g = tid + i * 512;
                int half = g >> 11, g3 = g & 2047;
                int krow = g3 >> 4, g16 = g3 & 15;
                int chunk = g16 >> 3, col16 = g16 & 7;
                const __nv_bfloat16* s = half ? csL : csH;
                cp16(sbase + (uint32_t)half * K5_CS_L + chunk * K5_CHUNK +
                         SW128(krow * 128 + col16 * 16),
                     s + (size_t)krow * NPIX + g16 * 8);
            }
        }
        k5_loadA(sbase, b, 0);

        float4 acc[2][2][2];
#pragma unroll
        for (int a = 0; a < 2; a++)
#pragma unroll
            for (int p = 0; p < 2; p++)
#pragma unroll
                for (int j = 0; j < 2; j++) acc[a][p][j] = make_float4(0.f, 0.f, 0.f, 0.f);

        for (int s = 0; s < 8; s++) {
            const int c0 = s >> 1, ksub = s & 1;
            asm volatile("cp.async.wait_group 0;" ::: "memory");
            __syncthreads();
            if (s + 1 < 8) k5_loadA(sbase, b, s + 1);

            const uint32_t abuf = sbase + K5_A0 + (uint32_t)(s & 1) * K5_ABUF;
            compute_tile2<2, true>(abuf, 16384, sbase, K5_CS_L,
                                   K5_CHUNK, ksub * 64, lane, wm, wn, acc);

            if (ksub == 1) {
#pragma unroll
                for (int mt = 0; mt < 2; mt++)
#pragma unroll
                    for (int ntp = 0; ntp < 2; ntp++)
#pragma unroll
                        for (int j = 0; j < 2; j++) {
                            int r = wm * 32 + mt * 16 + (lane >> 2);
                            int c = wn * 32 + ntp * 16 + j * 8 + (lane & 3) * 2;
                            float4 v = acc[mt][ntp][j];
                            float t0 = g_t[c0 * 128 + r];
                            float t1 = g_t[c0 * 128 + r + 8];
                            float* D = out + ((size_t)b * CCH + c0 * 128 + r) * NPIX + n0 + c;
                            *(float2*)D              = make_float2(v.x + t0, v.y + t0);
                            *(float2*)(D + 8 * NPIX) = make_float2(v.z + t1, v.w + t1);
                            acc[mt][ntp][j] = make_float4(0.f, 0.f, 0.f, 0.f);
                        }
            }
        }
        __syncthreads();   // drain before next tile reuses Cs region
    }
}

// ---------------------------------------------------------------------------
extern "C" void kernel_launch(void* const* d_in, const int* in_sizes, int n_in,
                              void* d_out, int out_size) {
    const float* x     = (const float*)d_in[0];
    const float* wA    = (const float*)d_in[1];
    const float* wB    = (const float*)d_in[2];
    const float* wC    = (const float*)d_in[3];
    const float* wProj = (const float*)d_in[4];
    const float* gamma = (const float*)d_in[5];
    const float* beta  = (const float*)d_in[6];
    const float* mean  = (const float*)d_in[7];
    const float* var   = (const float*)d_in[8];
    float* out = (float*)d_out;

    const int smem_128 = 2 * GeomT<128>::BUF;   // 128KB
    const int smem_k1  = 2 * K1BUF;             // 128KB
    cudaFuncSetAttribute(k1_gemm, cudaFuncAttributeMaxDynamicSharedMemorySize, smem_k1);
    cudaFuncSetAttribute(k3_gemm, cudaFuncAttributeMaxDynamicSharedMemorySize, smem_128);
    cudaFuncSetAttribute(k5_gemm, cudaFuncAttributeMaxDynamicSharedMemorySize, K5_SMEM);

    k_prep<<<1024, 256>>>(gamma, beta, mean, var, wA, wB, wC);
    k1_gemm<<<dim3(K1_GRID, 1, 1), 512, smem_k1>>>(x);
    k_softmax<<<4096, 256>>>();
    k3_gemm<<<dim3(BATCH, 8), 512, smem_128>>>();
    k_M2t<<<dim3(BATCH, CCH / 128), 256>>>(wProj);
    k5_gemm<<<dim3(K5_GRID, 1, 1), 512, K5_SMEM>>>(out);
}

// round 15
// speedup vs baseline: 1.1789x; 1.0851x over previous
#include <cuda_runtime.h>
#include <cuda_bf16.h>
#include <cstdint>

static constexpr int BATCH = 16;
static constexpr int CCH   = 512;
static constexpr int NPIX  = 4096;
static constexpr int HD    = 128;

// fp32 logits (pre-softmax) for A (idx 0) and C (idx 1)
__device__ float g_logits[(size_t)2 * BATCH * HD * NPIX];
// bf16 hi/lo operand stores (as u32 pair arrays)
__device__ uint32_t g_WH[3 * HD * CCH / 2],        g_WL[3 * HD * CCH / 2];
__device__ uint32_t g_BfH[(size_t)BATCH * HD * NPIX / 2],  g_BfL[(size_t)BATCH * HD * NPIX / 2];
__device__ uint32_t g_AmH[(size_t)BATCH * HD * NPIX / 2],  g_AmL[(size_t)BATCH * HD * NPIX / 2];
__device__ uint32_t g_CsH[(size_t)BATCH * HD * NPIX / 2],  g_CsL[(size_t)BATCH * HD * NPIX / 2];
__device__ uint32_t g_M2H[BATCH * CCH * HD / 2],   g_M2L[BATCH * CCH * HD / 2];
__device__ float g_G[BATCH * HD * HD];
__device__ float g_s[CCH];
__device__ float g_t[CCH];

// ---------------------------------------------------------------------------
__device__ __forceinline__ uint32_t smem_u32(const void* p) {
    uint32_t a;
    asm("{ .reg .u64 t; cvta.to.shared.u64 t, %1; cvt.u32.u64 %0, t; }" : "=r"(a) : "l"(p));
    return a;
}
__device__ __forceinline__ void bsplit(float x, __nv_bfloat16& h, __nv_bfloat16& l) {
    h = __float2bfloat16_rn(x);
    l = __float2bfloat16_rn(x - __bfloat162float(h));
}
__device__ __forceinline__ uint32_t packpair(__nv_bfloat16 a, __nv_bfloat16 b) {
    uint16_t au = *(uint16_t*)&a, bu = *(uint16_t*)&b;
    return (uint32_t)au | ((uint32_t)bu << 16);
}
__device__ __forceinline__ void cp16(uint32_t dst, const void* src) {
    asm volatile("cp.async.cg.shared.global [%0], [%1], 16;" :: "r"(dst), "l"(src));
}
#define SW128(off) ((off) ^ (((off) >> 3) & 0x70))

__device__ __forceinline__ void ldsm4(uint32_t (&r)[4], uint32_t addr) {
    asm volatile("ldmatrix.sync.aligned.m8n8.x4.shared.b16 {%0,%1,%2,%3}, [%4];"
                 : "=r"(r[0]), "=r"(r[1]), "=r"(r[2]), "=r"(r[3]) : "r"(addr));
}
__device__ __forceinline__ void ldsm4t(uint32_t (&r)[4], uint32_t addr) {
    asm volatile("ldmatrix.sync.aligned.m8n8.x4.trans.shared.b16 {%0,%1,%2,%3}, [%4];"
                 : "=r"(r[0]), "=r"(r[1]), "=r"(r[2]), "=r"(r[3]) : "r"(addr));
}
__device__ __forceinline__ void mma16(float4& d, const uint32_t* a, uint32_t b0, uint32_t b1) {
    asm volatile("mma.sync.aligned.m16n8k16.row.col.f32.bf16.bf16.f32 "
                 "{%0,%1,%2,%3},{%4,%5,%6,%7},{%8,%9},{%0,%1,%2,%3};"
                 : "+f"(d.x), "+f"(d.y), "+f"(d.z), "+f"(d.w)
                 : "r"(a[0]), "r"(a[1]), "r"(a[2]), "r"(a[3]), "r"(b0), "r"(b1));
}

// ---------------------------------------------------------------------------
// compute core: NP n16-groups per warp, BK=64, fragment reg double-buffering
// ---------------------------------------------------------------------------
static constexpr int SLAB_A = 16384;   // 128 rows x 128B

template<int NP, bool TRB>
__device__ __forceinline__ void compute_tile2(
    uint32_t abase, uint32_t ahalfoff,
    uint32_t bbase, uint32_t bhalfoff, int bchstride, int browoff,
    int lane, int wm, int wn, float4 (&acc)[2][NP][2]) {
    const int rl = lane & 15, gh = lane >> 4;
    constexpr int WN = NP * 16;

    uint32_t aH[2][2][4], aL[2][2][4];
    uint32_t bh[2][4], bl[2][4];

    auto loadA = [&](int ks, int buf) {
#pragma unroll
        for (int mt = 0; mt < 2; mt++) {
            uint32_t ar = abase + SW128((wm * 32 + mt * 16 + rl) * 128 + (ks * 2 + gh) * 16);
            ldsm4(aH[buf][mt], ar);
            ldsm4(aL[buf][mt], ar + ahalfoff);
        }
    };
    auto loadB = [&](int ks, int ntp, int buf) {
        if (!TRB) {
            uint32_t br = bbase + SW128((wn * WN + ntp * 16 + rl) * 128 + (ks * 2 + gh) * 16);
            ldsm4(bh[buf], br);
            ldsm4(bl[buf], br + bhalfoff);
        } else {
            int n = wn * WN + ntp * 16 + gh * 8;
            int chunk = n >> 6, col16 = (n & 63) >> 3;
            uint32_t br = bbase + chunk * bchstride +
                          SW128((browoff + ks * 16 + rl) * 128 + col16 * 16);
            ldsm4t(bh[buf], br);
            ldsm4t(bl[buf], br + bhalfoff);
        }
    };

    loadA(0, 0);
    loadB(0, 0, 0);
#pragma unroll
    for (int ks = 0; ks < 4; ks++) {
        const int ab = ks & 1;
#pragma unroll
        for (int ntp = 0; ntp < NP; ntp++) {
            const int bb = (ks * NP + ntp) & 1;
            if (ntp + 1 < NP) {
                loadB(ks, ntp + 1, (ks * NP + ntp + 1) & 1);
            } else if (ks + 1 < 4) {
                loadA(ks + 1, (ks + 1) & 1);
                loadB(ks + 1, 0, ((ks + 1) * NP) & 1);
            }
            uint32_t b0h[2], b1h[2], b0l[2], b1l[2];
#pragma unroll
            for (int j = 0; j < 2; j++) {
                b0h[j] = TRB ? bh[bb][2 * j]     : bh[bb][j];
                b1h[j] = TRB ? bh[bb][2 * j + 1] : bh[bb][j + 2];
                b0l[j] = TRB ? bl[bb][2 * j]     : bl[bb][j];
                b1l[j] = TRB ? bl[bb][2 * j + 1] : bl[bb][j + 2];
            }
#pragma unroll
            for (int j = 0; j < 2; j++)
#pragma unroll
                for (int mt = 0; mt < 2; mt++)
                    mma16(acc[mt][ntp][j], aH[ab][mt], b0h[j], b1h[j]);
#pragma unroll
            for (int j = 0; j < 2; j++)
#pragma unroll
                for (int mt = 0; mt < 2; mt++)
                    mma16(acc[mt][ntp][j], aH[ab][mt], b0l[j], b1l[j]);
#pragma unroll
            for (int j = 0; j < 2; j++)
#pragma unroll
                for (int mt = 0; mt < 2; mt++)
                    mma16(acc[mt][ntp][j], aL[ab][mt], b0h[j], b1h[j]);
        }
    }
}

// ---------------------------------------------------------------------------
// 256-thread GEMM stage: tile 128(M) x 64(N) x 64(K), stage = 48 KB
//   A hi @0 (16K), A lo @16K, B hi @32K (8K), B lo @40K (8K)
// ---------------------------------------------------------------------------
static constexpr int ST64   = 49152;   // stage size
static constexpr int B_OFF  = 32768;
static constexpr int B_HALF = 8192;

// A loader (128 rows x 64 k, hi+lo): 2048 cp16 / 256 thr = 8 iters
__device__ __forceinline__ void loadA64(uint32_t bufb, int kofs,
                                        const __nv_bfloat16* aH, const __nv_bfloat16* aL, int sA) {
    const int tid = threadIdx.x;
#pragma unroll
    for (int i = 0; i < 8; i++) {
        int g = tid + i * 256;
        int row_lin = g >> 3, gran = g & 7;
        const __nv_bfloat16* s = (row_lin < 128) ? aH : aL;
        int row = row_lin & 127;
        uint32_t slaboff = (row_lin < 128) ? 0u : (uint32_t)SLAB_A;
        cp16(bufb + slaboff + SW128(row * 128 + gran * 16),
             s + (size_t)row * sA + kofs + gran * 8);
    }
}

// B loader, k-major rows (k3): 64 n-rows x 64 k, hi+lo: 1024 cp16 / 256 = 4 iters
__device__ __forceinline__ void loadB64_n(uint32_t bufb, int kofs,
                                          const __nv_bfloat16* bH, const __nv_bfloat16* bL, int sB) {
    const int tid = threadIdx.x;
#pragma unroll
    for (int i = 0; i < 4; i++) {
        int g = tid + i * 256;
        int half = g >> 9, g3 = g & 511;
        int row = g3 >> 3, gran = g3 & 7;
        const __nv_bfloat16* s = half ? bL : bH;
        cp16(bufb + B_OFF + (uint32_t)half * B_HALF + SW128(row * 128 + gran * 16),
             s + (size_t)row * sB + kofs + gran * 8);
    }
}

// ---------------------------------------------------------------------------
// prep
// ---------------------------------------------------------------------------
__global__ void __launch_bounds__(256) k_prep(const float* __restrict__ gamma,
                                              const float* __restrict__ beta,
                                              const float* __restrict__ mean,
                                              const float* __restrict__ var,
                                              const float* __restrict__ wA,
                                              const float* __restrict__ wB,
                                              const float* __restrict__ wC) {
    int idx = blockIdx.x * 256 + threadIdx.x;
    if (idx < BATCH * HD * HD) g_G[idx] = 0.0f;
    if (idx < CCH) {
        float inv = rsqrtf(var[idx] + 1e-5f);
        float sc  = inv * gamma[idx];
        g_s[idx] = sc;
        g_t[idx] = beta[idx] - mean[idx] * sc;
    }
    if (idx < 3 * HD * CCH / 2) {
        const float* src = (idx < 32768) ? wA : (idx < 65536) ? wB : wC;
        int lp = idx & 32767;
        float f0 = src[2 * lp], f1 = src[2 * lp + 1];
        __nv_bfloat16 h0, l0, h1, l1;
        bsplit(f0, h0, l0); bsplit(f1, h1, l1);
        g_WH[idx] = packpair(h0, h1);
        g_WL[idx] = packpair(l0, l1);
    }
}

// ---------------------------------------------------------------------------
// K1: logits = W[w] @ x[b], 256 threads, tile 128x64, direct-x fused split.
// grid: 3072 CTAs (b x w x 64 n-tiles), w fastest for x L2 reuse.
// ---------------------------------------------------------------------------
__device__ __forceinline__ void k1_ldg_B(float (&st)[16], const float* xb, int kofs) {
    const int tid = threadIdx.x;
#pragma unroll
    for (int i = 0; i < 4; i++) {
        int idx = tid + i * 256;
        int krow = idx >> 4, ng4 = idx & 15;
        const float* p = xb + (size_t)(kofs + krow) * NPIX + ng4 * 4;
        asm volatile("ld.global.nc.v4.f32 {%0,%1,%2,%3}, [%4];"
                     : "=f"(st[4 * i]), "=f"(st[4 * i + 1]),
                       "=f"(st[4 * i + 2]), "=f"(st[4 * i + 3]) : "l"(p));
    }
}

__device__ __forceinline__ void k1_sts_B(uint32_t bufb, const float (&st)[16]) {
    const int tid = threadIdx.x;
    const uint32_t bsb = bufb + B_OFF;
#pragma unroll
    for (int i = 0; i < 4; i++) {
        int idx = tid + i * 256;
        int krow = idx >> 4, ng4 = idx & 15;
        uint32_t off = bsb + SW128((uint32_t)(krow * 128 + ng4 * 8));
        __nv_bfloat16 h0, l0, h1, l1, h2, l2, h3, l3;
        bsplit(st[4 * i],     h0, l0);
        bsplit(st[4 * i + 1], h1, l1);
        bsplit(st[4 * i + 2], h2, l2);
        bsplit(st[4 * i + 3], h3, l3);
        uint32_t hi01 = packpair(h0, h1), hi23 = packpair(h2, h3);
        uint32_t lo01 = packpair(l0, l1), lo23 = packpair(l2, l3);
        asm volatile("st.shared.v2.u32 [%0], {%1,%2};"
                     :: "r"(off), "r"(hi01), "r"(hi23) : "memory");
        asm volatile("st.shared.v2.u32 [%0], {%1,%2};"
                     :: "r"(off + B_HALF), "r"(lo01), "r"(lo23) : "memory");
    }
}

__global__ void __launch_bounds__(256, 2) k1_gemm(const float* __restrict__ x) {
    extern __shared__ uint32_t smem[];
    uint32_t sbase = smem_u32(smem);
    const int b  = blockIdx.x / 192;
    const int r192 = blockIdx.x % 192;
    const int w  = r192 % 3;
    const int n0 = (r192 / 3) * 64;
    const int tid = threadIdx.x;
    const int lane = tid & 31, wid = tid >> 5;
    const int wm = wid & 3, wn = wid >> 2;

    float4 acc[2][2][2];
#pragma unroll
    for (int a = 0; a < 2; a++)
#pragma unroll
        for (int p = 0; p < 2; p++)
#pragma unroll
            for (int j = 0; j < 2; j++) acc[a][p][j] = make_float4(0.f, 0.f, 0.f, 0.f);

    const __nv_bfloat16* aH = (const __nv_bfloat16*)g_WH + (size_t)w * HD * CCH;
    const __nv_bfloat16* aL = (const __nv_bfloat16*)g_WL + (size_t)w * HD * CCH;
    const float* xb = x + (size_t)b * CCH * NPIX + n0;

    const int KT = CCH / 64;   // 8
    float st[16];

    k1_ldg_B(st, xb, 0);
    loadA64(sbase, 0, aH, aL, CCH);
    asm volatile("cp.async.commit_group;" ::: "memory");
    k1_sts_B(sbase, st);

    for (int kt = 0; kt < KT; kt++) {
        asm volatile("cp.async.wait_group 0;" ::: "memory");
        __syncthreads();
        if (kt + 1 < KT) {
            k1_ldg_B(st, xb, (kt + 1) * 64);
            loadA64(sbase + ((kt + 1) & 1) * ST64, (kt + 1) * 64, aH, aL, CCH);
            asm volatile("cp.async.commit_group;" ::: "memory");
        }
        uint32_t bufb = sbase + (kt & 1) * ST64;
        compute_tile2<2, true>(bufb, SLAB_A, bufb + B_OFF, B_HALF,
                               B_HALF, 0, lane, wm, wn, acc);
        if (kt + 1 < KT)
            k1_sts_B(sbase + ((kt + 1) & 1) * ST64, st);
    }

#pragma unroll
    for (int mt = 0; mt < 2; mt++)
#pragma unroll
        for (int ntp = 0; ntp < 2; ntp++)
#pragma unroll
            for (int j = 0; j < 2; j++) {
                int r = wm * 32 + mt * 16 + (lane >> 2);
                int c = wn * 32 + ntp * 16 + j * 8 + (lane & 3) * 2;
                float4 v = acc[mt][ntp][j];
                if (w == 1) {
                    uint32_t* DH0 = g_BfH + ((size_t)b * HD + r) * (NPIX / 2) + (n0 + c) / 2;
                    uint32_t* DL0 = g_BfL + ((size_t)b * HD + r) * (NPIX / 2) + (n0 + c) / 2;
                    uint32_t* DH1 = DH0 + 8 * (NPIX / 2);
                    uint32_t* DL1 = DL0 + 8 * (NPIX / 2);
                    __nv_bfloat16 h0, l0, h1, l1;
                    bsplit(v.x, h0, l0); bsplit(v.y, h1, l1);
                    *DH0 = packpair(h0, h1); *DL0 = packpair(l0, l1);
                    bsplit(v.z, h0, l0); bsplit(v.w, h1, l1);
                    *DH1 = packpair(h0, h1); *DL1 = packpair(l0, l1);
                } else {
                    const int wlog = (w == 0) ? 0 : 1;
                    float* D = g_logits + (((size_t)wlog * BATCH + b) * HD + r) * NPIX + n0 + c;
                    *(float2*)D              = make_float2(v.x, v.y);
                    *(float2*)(D + 8 * NPIX) = make_float2(v.z, v.w);
                }
            }
}

// ---------------------------------------------------------------------------
// K2: row softmax with shuffle reductions
// ---------------------------------------------------------------------------
__global__ void __launch_bounds__(256) k_softmax() {
    int rid = blockIdx.x;                       // 0..4095
    int wlog = (rid < 2048) ? 0 : 1;
    int r = rid & 2047;                         // b*128 + h
    const float* p = g_logits + ((size_t)(wlog * 2048 + r)) * NPIX;
    int tid = threadIdx.x;
    const int lane = tid & 31, wrp = tid >> 5;
    __shared__ float wred[8];

    float4 v[4];
#pragma unroll
    for (int q = 0; q < 4; q++) v[q] = *(const float4*)(p + (q * 256 + tid) * 4);

    float m = v[0].x;
#pragma unroll
    for (int q = 0; q < 4; q++) {
        m = fmaxf(m, v[q].x); m = fmaxf(m, v[q].y);
        m = fmaxf(m, v[q].z); m = fmaxf(m, v[q].w);
    }
#pragma unroll
    for (int off = 16; off > 0; off >>= 1)
        m = fmaxf(m, __shfl_xor_sync(0xffffffffu, m, off));
    if (lane == 0) wred[wrp] = m;
    __syncthreads();
    float M = wred[0];
#pragma unroll
    for (int i = 1; i < 8; i++) M = fmaxf(M, wred[i]);
    __syncthreads();

    float ssum = 0.0f;
#pragma unroll
    for (int q = 0; q < 4; q++) {
        v[q].x = expf(v[q].x - M); ssum += v[q].x;
        v[q].y = expf(v[q].y - M); ssum += v[q].y;
        v[q].z = expf(v[q].z - M); ssum += v[q].z;
        v[q].w = expf(v[q].w - M); ssum += v[q].w;
    }
#pragma unroll
    for (int off = 16; off > 0; off >>= 1)
        ssum += __shfl_xor_sync(0xffffffffu, ssum, off);
    if (lane == 0) wred[wrp] = ssum;
    __syncthreads();
    float S = 0.0f;
#pragma unroll
    for (int i = 0; i < 8; i++) S += wred[i];
    float inv = 1.0f / S;

    uint32_t* AH = (wlog == 0 ? g_AmH : g_CsH) + (size_t)r * (NPIX / 2);
    uint32_t* AL = (wlog == 0 ? g_AmL : g_CsL) + (size_t)r * (NPIX / 2);
#pragma unroll
    for (int q = 0; q < 4; q++) {
        int n2 = (q * 256 + tid) * 2;
        float a0 = v[q].x * inv, a1 = v[q].y * inv;
        float a2 = v[q].z * inv, a3 = v[q].w * inv;
        __nv_bfloat16 h0, l0, h1, l1;
        bsplit(a0, h0, l0); bsplit(a1, h1, l1);
        AH[n2] = packpair(h0, h1); AL[n2] = packpair(l0, l1);
        bsplit(a2, h0, l0); bsplit(a3, h1, l1);
        AH[n2 + 1] = packpair(h0, h1); AL[n2 + 1] = packpair(l0, l1);
    }
}

// ---------------------------------------------------------------------------
// K3: G[b] += Bf[b] @ Am[b]^T, 256 threads, tile 128x64, 8-way k-split.
// grid (16 b, 16 = 8 ksplit x 2 n-half)
// ---------------------------------------------------------------------------
__global__ void __launch_bounds__(256, 2) k3_gemm() {
    extern __shared__ uint32_t smem[];
    uint32_t sbase = smem_u32(smem);
    const int b  = blockIdx.x;
    const int kb = (blockIdx.y >> 1) * 512;
    const int nh = (blockIdx.y & 1) * 64;
    const int tid = threadIdx.x;
    const int lane = tid & 31, wid = tid >> 5;
    const int wm = wid & 3, wn = wid >> 2;

    float4 acc[2][2][2];
#pragma unroll
    for (int a = 0; a < 2; a++)
#pragma unroll
        for (int p = 0; p < 2; p++)
#pragma unroll
            for (int j = 0; j < 2; j++) acc[a][p][j] = make_float4(0.f, 0.f, 0.f, 0.f);

    const __nv_bfloat16* aH = (const __nv_bfloat16*)g_BfH + (size_t)b * HD * NPIX + kb;
    const __nv_bfloat16* aL = (const __nv_bfloat16*)g_BfL + (size_t)b * HD * NPIX + kb;
    const __nv_bfloat16* bH = (const __nv_bfloat16*)g_AmH + ((size_t)b * HD + nh) * NPIX + kb;
    const __nv_bfloat16* bL = (const __nv_bfloat16*)g_AmL + ((size_t)b * HD + nh) * NPIX + kb;

    const int KT = 8;   // 512 / 64
    loadA64(sbase, 0, aH, aL, NPIX);
    loadB64_n(sbase, 0, bH, bL, NPIX);
    asm volatile("cp.async.commit_group;" ::: "memory");

    for (int kt = 0; kt < KT; kt++) {
        asm volatile("cp.async.wait_group 0;" ::: "memory");
        __syncthreads();
        if (kt + 1 < KT) {
            loadA64(sbase + ((kt + 1) & 1) * ST64, (kt + 1) * 64, aH, aL, NPIX);
            loadB64_n(sbase + ((kt + 1) & 1) * ST64, (kt + 1) * 64, bH, bL, NPIX);
            asm volatile("cp.async.commit_group;" ::: "memory");
        }
        uint32_t bufb = sbase + (kt & 1) * ST64;
        compute_tile2<2, false>(bufb, SLAB_A, bufb + B_OFF, B_HALF,
                                B_HALF, 0, lane, wm, wn, acc);
    }

    float* Gp = g_G + (size_t)b * HD * HD;
#pragma unroll
    for (int mt = 0; mt < 2; mt++)
#pragma unroll
        for (int ntp = 0; ntp < 2; ntp++)
#pragma unroll
            for (int j = 0; j < 2; j++) {
                int r = wm * 32 + mt * 16 + (lane >> 2);
                int c = nh + wn * 32 + ntp * 16 + j * 8 + (lane & 3) * 2;
                float4 v = acc[mt][ntp][j];
                atomicAdd(&Gp[r * HD + c],           v.x);
                atomicAdd(&Gp[r * HD + c + 1],       v.y);
                atomicAdd(&Gp[(r + 8) * HD + c],     v.z);
                atomicAdd(&Gp[(r + 8) * HD + c + 1], v.w);
            }
}

// ---------------------------------------------------------------------------
// K4: M2 = (s .* wProj) @ G  -> bf16 hi/lo [b][c][g]
// ---------------------------------------------------------------------------
__global__ void __launch_bounds__(256) k_M2t(const float* __restrict__ wProj) {
    __shared__ float As[16][128];
    __shared__ float Bs[16][128];
    const int b  = blockIdx.x;
    const int c0 = blockIdx.y * 128;
    const float* Gp = g_G + (size_t)b * HD * HD;
    const int tid = threadIdx.x;
    const int tx = tid & 15, ty = tid >> 4;

    float acc[8][8];
#pragma unroll
    for (int i = 0; i < 8; i++)
#pragma unroll
        for (int j = 0; j < 8; j++) acc[i][j] = 0.0f;

    for (int k0 = 0; k0 < HD; k0 += 16) {
#pragma unroll
        for (int s = tid; s < 512; s += 256) {
            int row = s >> 2, kq = (s & 3) << 2;
            float4 v = *(const float4*)(wProj + (size_t)(c0 + row) * HD + k0 + kq);
            As[kq + 0][row] = v.x; As[kq + 1][row] = v.y;
            As[kq + 2][row] = v.z; As[kq + 3][row] = v.w;
            int kr = s >> 5, nq = (s & 31) << 2;
            *(float4*)&Bs[kr][nq] = *(const float4*)(Gp + (size_t)(k0 + kr) * HD + nq);
        }
        __syncthreads();
#pragma unroll
        for (int k = 0; k < 16; k++) {
            float a[8], bb[8];
            *(float4*)(a)      = *(const float4*)&As[k][ty * 8];
            *(float4*)(a + 4)  = *(const float4*)&As[k][ty * 8 + 4];
            *(float4*)(bb)     = *(const float4*)&Bs[k][tx * 8];
            *(float4*)(bb + 4) = *(const float4*)&Bs[k][tx * 8 + 4];
#pragma unroll
            for (int i = 0; i < 8; i++)
#pragma unroll
                for (int j = 0; j < 8; j++) acc[i][j] = fmaf(a[i], bb[j], acc[i][j]);
        }
        __syncthreads();
    }
#pragma unroll
    for (int i = 0; i < 8; i++) {
        int c = c0 + ty * 8 + i;
        float sc = g_s[c];
        uint32_t* DH = g_M2H + ((size_t)b * CCH + c) * (HD / 2) + tx * 4;
        uint32_t* DL = g_M2L + ((size_t)b * CCH + c) * (HD / 2) + tx * 4;
#pragma unroll
        for (int j = 0; j < 4; j++) {
            float f0 = sc * acc[i][2 * j], f1 = sc * acc[i][2 * j + 1];
            __nv_bfloat16 h0, l0, h1, l1;
            bsplit(f0, h0, l0); bsplit(f1, h1, l1);
            DH[j] = packpair(h0, h1);
            DL[j] = packpair(l0, l1);
        }
    }
}

// ---------------------------------------------------------------------------
// K5: out[b] = M2[b] @ Cs[b] + t.  Resident Cs, 8 pipelined c/k steps.
// ---------------------------------------------------------------------------
static constexpr int K5_CHUNK = 16384;
static constexpr int K5_CS_L  = 32768;
static constexpr int K5_A0    = 65536;
static constexpr int K5_ABUF  = 32768;
static constexpr int K5_SMEM  = 65536 + 2 * 32768;   // 128 KB

__device__ __forceinline__ void k5_loadA(uint32_t sbase, int b, int s_idx) {
    const int tid = threadIdx.x;
    const int c0 = (s_idx >> 1) * 128, ks = (s_idx & 1) * 64;
    uint32_t abuf = sbase + K5_A0 + (uint32_t)(s_idx & 1) * K5_ABUF;
    const __nv_bfloat16* mH = (const __nv_bfloat16*)g_M2H + ((size_t)b * CCH + c0) * HD + ks;
    const __nv_bfloat16* mL = (const __nv_bfloat16*)g_M2L + ((size_t)b * CCH + c0) * HD + ks;
#pragma unroll
    for (int i = 0; i < 4; i++) {
        int g = tid + i * 512;
        int half = g >> 10, g3 = g & 1023;
        int row = g3 >> 3, gran = g3 & 7;
        const __nv_bfloat16* s = half ? mL : mH;
        cp16(abuf + (uint32_t)half * 16384 + SW128(row * 128 + gran * 16),
             s + (size_t)row * HD + gran * 8);
    }
    asm volatile("cp.async.commit_group;" ::: "memory");
}

__global__ void __launch_bounds__(512) k5_gemm(float* __restrict__ out) {
    extern __shared__ uint32_t smem[];
    uint32_t sbase = smem_u32(smem);
    const int b = blockIdx.z;
    const int n0 = blockIdx.x * 128;
    const int tid = threadIdx.x;
    const int lane = tid & 31, wid = tid >> 5;
    const int wm = wid & 3, wn = wid >> 2;

    {
        const __nv_bfloat16* csH = (const __nv_bfloat16*)g_CsH + (size_t)b * HD * NPIX + n0;
        const __nv_bfloat16* csL = (const __nv_bfloat16*)g_CsL + (size_t)b * HD * NPIX + n0;
#pragma unroll
        for (int i = 0; i < 8; i++) {
            int g = tid + i * 512;
            int half = g >> 11, g3 = g & 2047;
            int krow = g3 >> 4, g16 = g3 & 15;
            int chunk = g16 >> 3, col16 = g16 & 7;
            const __nv_bfloat16* s = half ? csL : csH;
            cp16(sbase + (uint32_t)half * K5_CS_L + chunk * K5_CHUNK +
                     SW128(krow * 128 + col16 * 16),
                 s + (size_t)krow * NPIX + g16 * 8);
        }
    }
    k5_loadA(sbase, b, 0);

    float4 acc[2][2][2];
#pragma unroll
    for (int a = 0; a < 2; a++)
#pragma unroll
        for (int p = 0; p < 2; p++)
#pragma unroll
            for (int j = 0; j < 2; j++) acc[a][p][j] = make_float4(0.f, 0.f, 0.f, 0.f);

    for (int s = 0; s < 8; s++) {
        const int c0 = s >> 1, ksub = s & 1;
        asm volatile("cp.async.wait_group 0;" ::: "memory");
        __syncthreads();
        if (s + 1 < 8) k5_loadA(sbase, b, s + 1);

        const uint32_t abuf = sbase + K5_A0 + (uint32_t)(s & 1) * K5_ABUF;
        compute_tile2<2, true>(abuf, 16384, sbase, K5_CS_L,
                               K5_CHUNK, ksub * 64, lane, wm, wn, acc);

        if (ksub == 1) {
#pragma unroll
            for (int mt = 0; mt < 2; mt++)
#pragma unroll
                for (int ntp = 0; ntp < 2; ntp++)
#pragma unroll
                    for (int j = 0; j < 2; j++) {
                        int r = wm * 32 + mt * 16 + (lane >> 2);
                        int c = wn * 32 + ntp * 16 + j * 8 + (lane & 3) * 2;
                        float4 v = acc[mt][ntp][j];
                        float t0 = g_t[c0 * 128 + r];
                        float t1 = g_t[c0 * 128 + r + 8];
                        float* D = out + ((size_t)b * CCH + c0 * 128 + r) * NPIX + n0 + c;
                        *(float2*)D              = make_float2(v.x + t0, v.y + t0);
                        *(float2*)(D + 8 * NPIX) = make_float2(v.z + t1, v.w + t1);
                        acc[mt][ntp][j] = make_float4(0.f, 0.f, 0.f, 0.f);
                    }
        }
    }
}

// ---------------------------------------------------------------------------
extern "C" void kernel_launch(void* const* d_in, const int* in_sizes, int n_in,
                              void* d_out, int out_size) {
    const float* x     = (const float*)d_in[0];
    const float* wA    = (const float*)d_in[1];
    const float* wB    = (const float*)d_in[2];
    const float* wC    = (const float*)d_in[3];
    const float* wProj = (const float*)d_in[4];
    const float* gamma = (const float*)d_in[5];
    const float* beta  = (const float*)d_in[6];
    const float* mean  = (const float*)d_in[7];
    const float* var   = (const float*)d_in[8];
    float* out = (float*)d_out;

    const int smem_64 = 2 * ST64;               // 96 KB  (2 CTAs/SM)
    cudaFuncSetAttribute(k1_gemm, cudaFuncAttributeMaxDynamicSharedMemorySize, smem_64);
    cudaFuncSetAttribute(k3_gemm, cudaFuncAttributeMaxDynamicSharedMemorySize, smem_64);
    cudaFuncSetAttribute(k5_gemm, cudaFuncAttributeMaxDynamicSharedMemorySize, K5_SMEM);

    k_prep<<<1024, 256>>>(gamma, beta, mean, var, wA, wB, wC);
    k1_gemm<<<dim3(3072, 1, 1), 256, smem_64>>>(x);
    k_softmax<<<4096, 256>>>();
    k3_gemm<<<dim3(BATCH, 16), 256, smem_64>>>();
    k_M2t<<<dim3(BATCH, CCH / 128), 256>>>(wProj);
    k5_gemm<<<dim3(32, 1, BATCH), 512, K5_SMEM>>>(out);
}

// round 16
// speedup vs baseline: 1.2283x; 1.0420x over previous
#include <cuda_runtime.h>
#include <cuda_bf16.h>
#include <cstdint>

static constexpr int BATCH = 16;
static constexpr int CCH   = 512;
static constexpr int NPIX  = 4096;
static constexpr int HD    = 128;

// fp32 logits (pre-softmax) for A (idx 0) and C (idx 1)
__device__ float g_logits[(size_t)2 * BATCH * HD * NPIX];
// bf16 hi/lo operand stores (as u32 pair arrays)
__device__ uint32_t g_WH[3 * HD * CCH / 2],        g_WL[3 * HD * CCH / 2];
__device__ uint32_t g_BfH[(size_t)BATCH * HD * NPIX / 2],  g_BfL[(size_t)BATCH * HD * NPIX / 2];
__device__ uint32_t g_AmH[(size_t)BATCH * HD * NPIX / 2],  g_AmL[(size_t)BATCH * HD * NPIX / 2];
__device__ uint32_t g_CsH[(size_t)BATCH * HD * NPIX / 2],  g_CsL[(size_t)BATCH * HD * NPIX / 2];
__device__ uint32_t g_M2H[BATCH * CCH * HD / 2],   g_M2L[BATCH * CCH * HD / 2];
__device__ float g_G[BATCH * HD * HD];
__device__ float g_s[CCH];
__device__ float g_t[CCH];

// ---------------------------------------------------------------------------
__device__ __forceinline__ uint32_t smem_u32(const void* p) {
    uint32_t a;
    asm("{ .reg .u64 t; cvta.to.shared.u64 t, %1; cvt.u32.u64 %0, t; }" : "=r"(a) : "l"(p));
    return a;
}
__device__ __forceinline__ void bsplit(float x, __nv_bfloat16& h, __nv_bfloat16& l) {
    h = __float2bfloat16_rn(x);
    l = __float2bfloat16_rn(x - __bfloat162float(h));
}
__device__ __forceinline__ uint32_t packpair(__nv_bfloat16 a, __nv_bfloat16 b) {
    uint16_t au = *(uint16_t*)&a, bu = *(uint16_t*)&b;
    return (uint32_t)au | ((uint32_t)bu << 16);
}
__device__ __forceinline__ void cp16(uint32_t dst, const void* src) {
    asm volatile("cp.async.cg.shared.global [%0], [%1], 16;" :: "r"(dst), "l"(src));
}
#define SW128(off) ((off) ^ (((off) >> 3) & 0x70))

__device__ __forceinline__ void ldsm4(uint32_t (&r)[4], uint32_t addr) {
    asm volatile("ldmatrix.sync.aligned.m8n8.x4.shared.b16 {%0,%1,%2,%3}, [%4];"
                 : "=r"(r[0]), "=r"(r[1]), "=r"(r[2]), "=r"(r[3]) : "r"(addr));
}
__device__ __forceinline__ void ldsm4t(uint32_t (&r)[4], uint32_t addr) {
    asm volatile("ldmatrix.sync.aligned.m8n8.x4.trans.shared.b16 {%0,%1,%2,%3}, [%4];"
                 : "=r"(r[0]), "=r"(r[1]), "=r"(r[2]), "=r"(r[3]) : "r"(addr));
}
__device__ __forceinline__ void mma16(float4& d, const uint32_t* a, uint32_t b0, uint32_t b1) {
    asm volatile("mma.sync.aligned.m16n8k16.row.col.f32.bf16.bf16.f32 "
                 "{%0,%1,%2,%3},{%4,%5,%6,%7},{%8,%9},{%0,%1,%2,%3};"
                 : "+f"(d.x), "+f"(d.y), "+f"(d.z), "+f"(d.w)
                 : "r"(a[0]), "r"(a[1]), "r"(a[2]), "r"(a[3]), "r"(b0), "r"(b1));
}

// ---------------------------------------------------------------------------
// compute core: NP n16-groups per warp, BK=64, fragment reg double-buffering
// ---------------------------------------------------------------------------
static constexpr int SLAB_A = 16384;   // 128 rows x 128B

template<int NP, bool TRB>
__device__ __forceinline__ void compute_tile2(
    uint32_t abase, uint32_t ahalfoff,
    uint32_t bbase, uint32_t bhalfoff, int bchstride, int browoff,
    int lane, int wm, int wn, float4 (&acc)[2][NP][2]) {
    const int rl = lane & 15, gh = lane >> 4;
    constexpr int WN = NP * 16;

    uint32_t aH[2][2][4], aL[2][2][4];
    uint32_t bh[2][4], bl[2][4];

    auto loadA = [&](int ks, int buf) {
#pragma unroll
        for (int mt = 0; mt < 2; mt++) {
            uint32_t ar = abase + SW128((wm * 32 + mt * 16 + rl) * 128 + (ks * 2 + gh) * 16);
            ldsm4(aH[buf][mt], ar);
            ldsm4(aL[buf][mt], ar + ahalfoff);
        }
    };
    auto loadB = [&](int ks, int ntp, int buf) {
        if (!TRB) {
            uint32_t br = bbase + SW128((wn * WN + ntp * 16 + rl) * 128 + (ks * 2 + gh) * 16);
            ldsm4(bh[buf], br);
            ldsm4(bl[buf], br + bhalfoff);
        } else {
            int n = wn * WN + ntp * 16 + gh * 8;
            int chunk = n >> 6, col16 = (n & 63) >> 3;
            uint32_t br = bbase + chunk * bchstride +
                          SW128((browoff + ks * 16 + rl) * 128 + col16 * 16);
            ldsm4t(bh[buf], br);
            ldsm4t(bl[buf], br + bhalfoff);
        }
    };

    loadA(0, 0);
    loadB(0, 0, 0);
#pragma unroll
    for (int ks = 0; ks < 4; ks++) {
        const int ab = ks & 1;
#pragma unroll
        for (int ntp = 0; ntp < NP; ntp++) {
            const int bb = (ks * NP + ntp) & 1;
            if (ntp + 1 < NP) {
                loadB(ks, ntp + 1, (ks * NP + ntp + 1) & 1);
            } else if (ks + 1 < 4) {
                loadA(ks + 1, (ks + 1) & 1);
                loadB(ks + 1, 0, ((ks + 1) * NP) & 1);
            }
            uint32_t b0h[2], b1h[2], b0l[2], b1l[2];
#pragma unroll
            for (int j = 0; j < 2; j++) {
                b0h[j] = TRB ? bh[bb][2 * j]     : bh[bb][j];
                b1h[j] = TRB ? bh[bb][2 * j + 1] : bh[bb][j + 2];
                b0l[j] = TRB ? bl[bb][2 * j]     : bl[bb][j];
                b1l[j] = TRB ? bl[bb][2 * j + 1] : bl[bb][j + 2];
            }
#pragma unroll
            for (int j = 0; j < 2; j++)
#pragma unroll
                for (int mt = 0; mt < 2; mt++)
                    mma16(acc[mt][ntp][j], aH[ab][mt], b0h[j], b1h[j]);
#pragma unroll
            for (int j = 0; j < 2; j++)
#pragma unroll
                for (int mt = 0; mt < 2; mt++)
                    mma16(acc[mt][ntp][j], aH[ab][mt], b0l[j], b1l[j]);
#pragma unroll
            for (int j = 0; j < 2; j++)
#pragma unroll
                for (int mt = 0; mt < 2; mt++)
                    mma16(acc[mt][ntp][j], aL[ab][mt], b0h[j], b1h[j]);
        }
    }
}

// ---------------------------------------------------------------------------
// 256-thread GEMM stage: tile 128(M) x 64(N) x 64(K), stage = 48 KB
//   A hi @0 (16K), A lo @16K, B hi @32K (8K), B lo @40K (8K)
// ---------------------------------------------------------------------------
static constexpr int ST64   = 49152;
static constexpr int B_OFF  = 32768;
static constexpr int B_HALF = 8192;

__device__ __forceinline__ void loadA64(uint32_t bufb, int kofs,
                                        const __nv_bfloat16* aH, const __nv_bfloat16* aL, int sA) {
    const int tid = threadIdx.x;
#pragma unroll
    for (int i = 0; i < 8; i++) {
        int g = tid + i * 256;
        int row_lin = g >> 3, gran = g & 7;
        const __nv_bfloat16* s = (row_lin < 128) ? aH : aL;
        int row = row_lin & 127;
        uint32_t slaboff = (row_lin < 128) ? 0u : (uint32_t)SLAB_A;
        cp16(bufb + slaboff + SW128(row * 128 + gran * 16),
             s + (size_t)row * sA + kofs + gran * 8);
    }
}

// B loader, k-major rows (k3): 64 n-rows x 64 k, hi+lo
__device__ __forceinline__ void loadB64_n(uint32_t bufb, int kofs,
                                          const __nv_bfloat16* bH, const __nv_bfloat16* bL, int sB) {
    const int tid = threadIdx.x;
#pragma unroll
    for (int i = 0; i < 4; i++) {
        int g = tid + i * 256;
        int half = g >> 9, g3 = g & 511;
        int row = g3 >> 3, gran = g3 & 7;
        const __nv_bfloat16* s = half ? bL : bH;
        cp16(bufb + B_OFF + (uint32_t)half * B_HALF + SW128(row * 128 + gran * 16),
             s + (size_t)row * sB + kofs + gran * 8);
    }
}

// B loader, TRB (k5): 64 k-rows x 64 n (one chunk), hi+lo
__device__ __forceinline__ void loadB64_t(uint32_t bufb, int kofs,
                                          const __nv_bfloat16* bH, const __nv_bfloat16* bL, int sB) {
    const int tid = threadIdx.x;
#pragma unroll
    for (int i = 0; i < 4; i++) {
        int g = tid + i * 256;
        int half = g >> 9, g3 = g & 511;
        int krow = g3 >> 3, gran = g3 & 7;
        const __nv_bfloat16* s = half ? bL : bH;
        cp16(bufb + B_OFF + (uint32_t)half * B_HALF + SW128(krow * 128 + gran * 16),
             s + (size_t)(kofs + krow) * sB + gran * 8);
    }
}

// ---------------------------------------------------------------------------
// prep
// ---------------------------------------------------------------------------
__global__ void __launch_bounds__(256) k_prep(const float* __restrict__ gamma,
                                              const float* __restrict__ beta,
                                              const float* __restrict__ mean,
                                              const float* __restrict__ var,
                                              const float* __restrict__ wA,
                                              const float* __restrict__ wB,
                                              const float* __restrict__ wC) {
    int idx = blockIdx.x * 256 + threadIdx.x;
    if (idx < BATCH * HD * HD) g_G[idx] = 0.0f;
    if (idx < CCH) {
        float inv = rsqrtf(var[idx] + 1e-5f);
        float sc  = inv * gamma[idx];
        g_s[idx] = sc;
        g_t[idx] = beta[idx] - mean[idx] * sc;
    }
    if (idx < 3 * HD * CCH / 2) {
        const float* src = (idx < 32768) ? wA : (idx < 65536) ? wB : wC;
        int lp = idx & 32767;
        float f0 = src[2 * lp], f1 = src[2 * lp + 1];
        __nv_bfloat16 h0, l0, h1, l1;
        bsplit(f0, h0, l0); bsplit(f1, h1, l1);
        g_WH[idx] = packpair(h0, h1);
        g_WL[idx] = packpair(l0, l1);
    }
}

// ---------------------------------------------------------------------------
// K1: logits = W[w] @ x[b], 256 threads, tile 128x64, direct-x fused split.
// ---------------------------------------------------------------------------
__device__ __forceinline__ void k1_ldg_B(float (&st)[16], const float* xb, int kofs) {
    const int tid = threadIdx.x;
#pragma unroll
    for (int i = 0; i < 4; i++) {
        int idx = tid + i * 256;
        int krow = idx >> 4, ng4 = idx & 15;
        const float* p = xb + (size_t)(kofs + krow) * NPIX + ng4 * 4;
        asm volatile("ld.global.nc.v4.f32 {%0,%1,%2,%3}, [%4];"
                     : "=f"(st[4 * i]), "=f"(st[4 * i + 1]),
                       "=f"(st[4 * i + 2]), "=f"(st[4 * i + 3]) : "l"(p));
    }
}

__device__ __forceinline__ void k1_sts_B(uint32_t bufb, const float (&st)[16]) {
    const int tid = threadIdx.x;
    const uint32_t bsb = bufb + B_OFF;
#pragma unroll
    for (int i = 0; i < 4; i++) {
        int idx = tid + i * 256;
        int krow = idx >> 4, ng4 = idx & 15;
        uint32_t off = bsb + SW128((uint32_t)(krow * 128 + ng4 * 8));
        __nv_bfloat16 h0, l0, h1, l1, h2, l2, h3, l3;
        bsplit(st[4 * i],     h0, l0);
        bsplit(st[4 * i + 1], h1, l1);
        bsplit(st[4 * i + 2], h2, l2);
        bsplit(st[4 * i + 3], h3, l3);
        uint32_t hi01 = packpair(h0, h1), hi23 = packpair(h2, h3);
        uint32_t lo01 = packpair(l0, l1), lo23 = packpair(l2, l3);
        asm volatile("st.shared.v2.u32 [%0], {%1,%2};"
                     :: "r"(off), "r"(hi01), "r"(hi23) : "memory");
        asm volatile("st.shared.v2.u32 [%0], {%1,%2};"
                     :: "r"(off + B_HALF), "r"(lo01), "r"(lo23) : "memory");
    }
}

__global__ void __launch_bounds__(256, 2) k1_gemm(const float* __restrict__ x) {
    extern __shared__ uint32_t smem[];
    uint32_t sbase = smem_u32(smem);
    const int b  = blockIdx.x / 192;
    const int r192 = blockIdx.x % 192;
    const int w  = r192 % 3;
    const int n0 = (r192 / 3) * 64;
    const int tid = threadIdx.x;
    const int lane = tid & 31, wid = tid >> 5;
    const int wm = wid & 3, wn = wid >> 2;

    float4 acc[2][2][2];
#pragma unroll
    for (int a = 0; a < 2; a++)
#pragma unroll
        for (int p = 0; p < 2; p++)
#pragma unroll
            for (int j = 0; j < 2; j++) acc[a][p][j] = make_float4(0.f, 0.f, 0.f, 0.f);

    const __nv_bfloat16* aH = (const __nv_bfloat16*)g_WH + (size_t)w * HD * CCH;
    const __nv_bfloat16* aL = (const __nv_bfloat16*)g_WL + (size_t)w * HD * CCH;
    const float* xb = x + (size_t)b * CCH * NPIX + n0;

    const int KT = CCH / 64;   // 8
    float st[16];

    k1_ldg_B(st, xb, 0);
    loadA64(sbase, 0, aH, aL, CCH);
    asm volatile("cp.async.commit_group;" ::: "memory");
    k1_sts_B(sbase, st);

    for (int kt = 0; kt < KT; kt++) {
        asm volatile("cp.async.wait_group 0;" ::: "memory");
        __syncthreads();
        if (kt + 1 < KT) {
            k1_ldg_B(st, xb, (kt + 1) * 64);
            loadA64(sbase + ((kt + 1) & 1) * ST64, (kt + 1) * 64, aH, aL, CCH);
            asm volatile("cp.async.commit_group;" ::: "memory");
        }
        uint32_t bufb = sbase + (kt & 1) * ST64;
        compute_tile2<2, true>(bufb, SLAB_A, bufb + B_OFF, B_HALF,
                               B_HALF, 0, lane, wm, wn, acc);
        if (kt + 1 < KT)
            k1_sts_B(sbase + ((kt + 1) & 1) * ST64, st);
    }

#pragma unroll
    for (int mt = 0; mt < 2; mt++)
#pragma unroll
        for (int ntp = 0; ntp < 2; ntp++)
#pragma unroll
            for (int j = 0; j < 2; j++) {
                int r = wm * 32 + mt * 16 + (lane >> 2);
                int c = wn * 32 + ntp * 16 + j * 8 + (lane & 3) * 2;
                float4 v = acc[mt][ntp][j];
                if (w == 1) {
                    uint32_t* DH0 = g_BfH + ((size_t)b * HD + r) * (NPIX / 2) + (n0 + c) / 2;
                    uint32_t* DL0 = g_BfL + ((size_t)b * HD + r) * (NPIX / 2) + (n0 + c) / 2;
                    uint32_t* DH1 = DH0 + 8 * (NPIX / 2);
                    uint32_t* DL1 = DL0 + 8 * (NPIX / 2);
                    __nv_bfloat16 h0, l0, h1, l1;
                    bsplit(v.x, h0, l0); bsplit(v.y, h1, l1);
                    *DH0 = packpair(h0, h1); *DL0 = packpair(l0, l1);
                    bsplit(v.z, h0, l0); bsplit(v.w, h1, l1);
                    *DH1 = packpair(h0, h1); *DL1 = packpair(l0, l1);
                } else {
                    const int wlog = (w == 0) ? 0 : 1;
                    float* D = g_logits + (((size_t)wlog * BATCH + b) * HD + r) * NPIX + n0 + c;
                    *(float2*)D              = make_float2(v.x, v.y);
                    *(float2*)(D + 8 * NPIX) = make_float2(v.z, v.w);
                }
            }
}

// ---------------------------------------------------------------------------
// K2: row softmax with shuffle reductions
// ---------------------------------------------------------------------------
__global__ void __launch_bounds__(256) k_softmax() {
    int rid = blockIdx.x;                       // 0..4095
    int wlog = (rid < 2048) ? 0 : 1;
    int r = rid & 2047;                         // b*128 + h
    const float* p = g_logits + ((size_t)(wlog * 2048 + r)) * NPIX;
    int tid = threadIdx.x;
    const int lane = tid & 31, wrp = tid >> 5;
    __shared__ float wred[8];

    float4 v[4];
#pragma unroll
    for (int q = 0; q < 4; q++) v[q] = *(const float4*)(p + (q * 256 + tid) * 4);

    float m = v[0].x;
#pragma unroll
    for (int q = 0; q < 4; q++) {
        m = fmaxf(m, v[q].x); m = fmaxf(m, v[q].y);
        m = fmaxf(m, v[q].z); m = fmaxf(m, v[q].w);
    }
#pragma unroll
    for (int off = 16; off > 0; off >>= 1)
        m = fmaxf(m, __shfl_xor_sync(0xffffffffu, m, off));
    if (lane == 0) wred[wrp] = m;
    __syncthreads();
    float M = wred[0];
#pragma unroll
    for (int i = 1; i < 8; i++) M = fmaxf(M, wred[i]);
    __syncthreads();

    float ssum = 0.0f;
#pragma unroll
    for (int q = 0; q < 4; q++) {
        v[q].x = expf(v[q].x - M); ssum += v[q].x;
        v[q].y = expf(v[q].y - M); ssum += v[q].y;
        v[q].z = expf(v[q].z - M); ssum += v[q].z;
        v[q].w = expf(v[q].w - M); ssum += v[q].w;
    }
#pragma unroll
    for (int off = 16; off > 0; off >>= 1)
        ssum += __shfl_xor_sync(0xffffffffu, ssum, off);
    if (lane == 0) wred[wrp] = ssum;
    __syncthreads();
    float S = 0.0f;
#pragma unroll
    for (int i = 0; i < 8; i++) S += wred[i];
    float inv = 1.0f / S;

    uint32_t* AH = (wlog == 0 ? g_AmH : g_CsH) + (size_t)r * (NPIX / 2);
    uint32_t* AL = (wlog == 0 ? g_AmL : g_CsL) + (size_t)r * (NPIX / 2);
#pragma unroll
    for (int q = 0; q < 4; q++) {
        int n2 = (q * 256 + tid) * 2;
        float a0 = v[q].x * inv, a1 = v[q].y * inv;
        float a2 = v[q].z * inv, a3 = v[q].w * inv;
        __nv_bfloat16 h0, l0, h1, l1;
        bsplit(a0, h0, l0); bsplit(a1, h1, l1);
        AH[n2] = packpair(h0, h1); AL[n2] = packpair(l0, l1);
        bsplit(a2, h0, l0); bsplit(a3, h1, l1);
        AH[n2 + 1] = packpair(h0, h1); AL[n2 + 1] = packpair(l0, l1);
    }
}

// ---------------------------------------------------------------------------
// K3: G[b] += Bf[b] @ Am[b]^T, 256 threads, tile 128x64, 16-way k-split.
// grid (16 b, 32 = 16 ksplit x 2 n-half)
// ---------------------------------------------------------------------------
__global__ void __launch_bounds__(256, 2) k3_gemm() {
    extern __shared__ uint32_t smem[];
    uint32_t sbase = smem_u32(smem);
    const int b  = blockIdx.x;
    const int kb = (blockIdx.y >> 1) * 256;
    const int nh = (blockIdx.y & 1) * 64;
    const int tid = threadIdx.x;
    const int lane = tid & 31, wid = tid >> 5;
    const int wm = wid & 3, wn = wid >> 2;

    float4 acc[2][2][2];
#pragma unroll
    for (int a = 0; a < 2; a++)
#pragma unroll
        for (int p = 0; p < 2; p++)
#pragma unroll
            for (int j = 0; j < 2; j++) acc[a][p][j] = make_float4(0.f, 0.f, 0.f, 0.f);

    const __nv_bfloat16* aH = (const __nv_bfloat16*)g_BfH + (size_t)b * HD * NPIX + kb;
    const __nv_bfloat16* aL = (const __nv_bfloat16*)g_BfL + (size_t)b * HD * NPIX + kb;
    const __nv_bfloat16* bH = (const __nv_bfloat16*)g_AmH + ((size_t)b * HD + nh) * NPIX + kb;
    const __nv_bfloat16* bL = (const __nv_bfloat16*)g_AmL + ((size_t)b * HD + nh) * NPIX + kb;

    const int KT = 4;   // 256 / 64
    loadA64(sbase, 0, aH, aL, NPIX);
    loadB64_n(sbase, 0, bH, bL, NPIX);
    asm volatile("cp.async.commit_group;" ::: "memory");

    for (int kt = 0; kt < KT; kt++) {
        asm volatile("cp.async.wait_group 0;" ::: "memory");
        __syncthreads();
        if (kt + 1 < KT) {
            loadA64(sbase + ((kt + 1) & 1) * ST64, (kt + 1) * 64, aH, aL, NPIX);
            loadB64_n(sbase + ((kt + 1) & 1) * ST64, (kt + 1) * 64, bH, bL, NPIX);
            asm volatile("cp.async.commit_group;" ::: "memory");
        }
        uint32_t bufb = sbase + (kt & 1) * ST64;
        compute_tile2<2, false>(bufb, SLAB_A, bufb + B_OFF, B_HALF,
                                B_HALF, 0, lane, wm, wn, acc);
    }

    float* Gp = g_G + (size_t)b * HD * HD;
#pragma unroll
    for (int mt = 0; mt < 2; mt++)
#pragma unroll
        for (int ntp = 0; ntp < 2; ntp++)
#pragma unroll
            for (int j = 0; j < 2; j++) {
                int r = wm * 32 + mt * 16 + (lane >> 2);
                int c = nh + wn * 32 + ntp * 16 + j * 8 + (lane & 3) * 2;
                float4 v = acc[mt][ntp][j];
                atomicAdd(&Gp[r * HD + c],           v.x);
                atomicAdd(&Gp[r * HD + c + 1],       v.y);
                atomicAdd(&Gp[(r + 8) * HD + c],     v.z);
                atomicAdd(&Gp[(r + 8) * HD + c + 1], v.w);
            }
}

// ---------------------------------------------------------------------------
// K4: M2 = (s .* wProj) @ G  -> bf16 hi/lo [b][c][g]
// ---------------------------------------------------------------------------
__global__ void __launch_bounds__(256) k_M2t(const float* __restrict__ wProj) {
    __shared__ float As[16][128];
    __shared__ float Bs[16][128];
    const int b  = blockIdx.x;
    const int c0 = blockIdx.y * 128;
    const float* Gp = g_G + (size_t)b * HD * HD;
    const int tid = threadIdx.x;
    const int tx = tid & 15, ty = tid >> 4;

    float acc[8][8];
#pragma unroll
    for (int i = 0; i < 8; i++)
#pragma unroll
        for (int j = 0; j < 8; j++) acc[i][j] = 0.0f;

    for (int k0 = 0; k0 < HD; k0 += 16) {
#pragma unroll
        for (int s = tid; s < 512; s += 256) {
            int row = s >> 2, kq = (s & 3) << 2;
            float4 v = *(const float4*)(wProj + (size_t)(c0 + row) * HD + k0 + kq);
            As[kq + 0][row] = v.x; As[kq + 1][row] = v.y;
            As[kq + 2][row] = v.z; As[kq + 3][row] = v.w;
            int kr = s >> 5, nq = (s & 31) << 2;
            *(float4*)&Bs[kr][nq] = *(const float4*)(Gp + (size_t)(k0 + kr) * HD + nq);
        }
        __syncthreads();
#pragma unroll
        for (int k = 0; k < 16; k++) {
            float a[8], bb[8];
            *(float4*)(a)      = *(const float4*)&As[k][ty * 8];
            *(float4*)(a + 4)  = *(const float4*)&As[k][ty * 8 + 4];
            *(float4*)(bb)     = *(const float4*)&Bs[k][tx * 8];
            *(float4*)(bb + 4) = *(const float4*)&Bs[k][tx * 8 + 4];
#pragma unroll
            for (int i = 0; i < 8; i++)
#pragma unroll
                for (int j = 0; j < 8; j++) acc[i][j] = fmaf(a[i], bb[j], acc[i][j]);
        }
        __syncthreads();
    }
#pragma unroll
    for (int i = 0; i < 8; i++) {
        int c = c0 + ty * 8 + i;
        float sc = g_s[c];
        uint32_t* DH = g_M2H + ((size_t)b * CCH + c) * (HD / 2) + tx * 4;
        uint32_t* DL = g_M2L + ((size_t)b * CCH + c) * (HD / 2) + tx * 4;
#pragma unroll
        for (int j = 0; j < 4; j++) {
            float f0 = sc * acc[i][2 * j], f1 = sc * acc[i][2 * j + 1];
            __nv_bfloat16 h0, l0, h1, l1;
            bsplit(f0, h0, l0); bsplit(f1, h1, l1);
            DH[j] = packpair(h0, h1);
            DL[j] = packpair(l0, l1);
        }
    }
}

// ---------------------------------------------------------------------------
// K5: out[b] = M2[b] @ Cs[b] + t.  256 threads, tile 128(c)x64(n), KT=2,
// 2 CTAs/SM.  c-tile fastest in grid for Cs L2 reuse.
// ---------------------------------------------------------------------------
__global__ void __launch_bounds__(256, 2) k5_gemm(float* __restrict__ out) {
    extern __shared__ uint32_t smem[];
    uint32_t sbase = smem_u32(smem);
    const int b  = blockIdx.y;
    const int c0 = (blockIdx.x & 3) * 128;
    const int n0 = (blockIdx.x >> 2) * 64;
    const int tid = threadIdx.x;
    const int lane = tid & 31, wid = tid >> 5;
    const int wm = wid & 3, wn = wid >> 2;

    float4 acc[2][2][2];
#pragma unroll
    for (int a = 0; a < 2; a++)
#pragma unroll
        for (int p = 0; p < 2; p++)
#pragma unroll
            for (int j = 0; j < 2; j++) acc[a][p][j] = make_float4(0.f, 0.f, 0.f, 0.f);

    const __nv_bfloat16* aH = (const __nv_bfloat16*)g_M2H + ((size_t)b * CCH + c0) * HD;
    const __nv_bfloat16* aL = (const __nv_bfloat16*)g_M2L + ((size_t)b * CCH + c0) * HD;
    const __nv_bfloat16* bH = (const __nv_bfloat16*)g_CsH + (size_t)b * HD * NPIX + n0;
    const __nv_bfloat16* bL = (const __nv_bfloat16*)g_CsL + (size_t)b * HD * NPIX + n0;

    const int KT = 2;   // 128 / 64
    loadA64(sbase, 0, aH, aL, HD);
    loadB64_t(sbase, 0, bH, bL, NPIX);
    asm volatile("cp.async.commit_group;" ::: "memory");

    for (int kt = 0; kt < KT; kt++) {
        asm volatile("cp.async.wait_group 0;" ::: "memory");
        __syncthreads();
        if (kt + 1 < KT) {
            loadA64(sbase + ((kt + 1) & 1) * ST64, (kt + 1) * 64, aH, aL, HD);
            loadB64_t(sbase + ((kt + 1) & 1) * ST64, (kt + 1) * 64, bH, bL, NPIX);
            asm volatile("cp.async.commit_group;" ::: "memory");
        }
        uint32_t bufb = sbase + (kt & 1) * ST64;
        compute_tile2<2, true>(bufb, SLAB_A, bufb + B_OFF, B_HALF,
                               B_HALF, 0, lane, wm, wn, acc);
    }

#pragma unroll
    for (int mt = 0; mt < 2; mt++)
#pragma unroll
        for (int ntp = 0; ntp < 2; ntp++)
#pragma unroll
            for (int j = 0; j < 2; j++) {
                int r = wm * 32 + mt * 16 + (lane >> 2);
                int c = wn * 32 + ntp * 16 + j * 8 + (lane & 3) * 2;
                float4 v = acc[mt][ntp][j];
                float t0 = g_t[c0 + r];
                float t1 = g_t[c0 + r + 8];
                float* D = out + ((size_t)b * CCH + c0 + r) * NPIX + n0 + c;
                *(float2*)D              = make_float2(v.x + t0, v.y + t0);
                *(float2*)(D + 8 * NPIX) = make_float2(v.z + t1, v.w + t1);
            }
}

// ---------------------------------------------------------------------------
extern "C" void kernel_launch(void* const* d_in, const int* in_sizes, int n_in,
                              void* d_out, int out_size) {
    const float* x     = (const float*)d_in[0];
    const float* wA    = (const float*)d_in[1];
    const float* wB    = (const float*)d_in[2];
    const float* wC    = (const float*)d_in[3];
    const float* wProj = (const float*)d_in[4];
    const float* gamma = (const float*)d_in[5];
    const float* beta  = (const float*)d_in[6];
    const float* mean  = (const float*)d_in[7];
    const float* var   = (const float*)d_in[8];
    float* out = (float*)d_out;

    const int smem_64 = 2 * ST64;               // 96 KB  (2 CTAs/SM)
    cudaFuncSetAttribute(k1_gemm, cudaFuncAttributeMaxDynamicSharedMemorySize, smem_64);
    cudaFuncSetAttribute(k3_gemm, cudaFuncAttributeMaxDynamicSharedMemorySize, smem_64);
    cudaFuncSetAttribute(k5_gemm, cudaFuncAttributeMaxDynamicSharedMemorySize, smem_64);

    k_prep<<<1024, 256>>>(gamma, beta, mean, var, wA, wB, wC);
    k1_gemm<<<dim3(3072, 1, 1), 256, smem_64>>>(x);
    k_softmax<<<4096, 256>>>();
    k3_gemm<<<dim3(BATCH, 32), 256, smem_64>>>();
    k_M2t<<<dim3(BATCH, CCH / 128), 256>>>(wProj);
    k5_gemm<<<dim3(256, BATCH, 1), 256, smem_64>>>(out);
}

// round 17
// speedup vs baseline: 1.2372x; 1.0072x over previous
#include <cuda_runtime.h>
#include <cuda_bf16.h>
#include <cstdint>

static constexpr int BATCH = 16;
static constexpr int CCH   = 512;
static constexpr int NPIX  = 4096;
static constexpr int HD    = 128;

// fp32 logits (pre-softmax) for A (idx 0) and C (idx 1)
__device__ float g_logits[(size_t)2 * BATCH * HD * NPIX];
// bf16 hi/lo operand stores (as u32 pair arrays)
__device__ uint32_t g_WH[3 * HD * CCH / 2],        g_WL[3 * HD * CCH / 2];
__device__ uint32_t g_BfH[(size_t)BATCH * HD * NPIX / 2],  g_BfL[(size_t)BATCH * HD * NPIX / 2];
__device__ uint32_t g_AmH[(size_t)BATCH * HD * NPIX / 2],  g_AmL[(size_t)BATCH * HD * NPIX / 2];
__device__ uint32_t g_CsH[(size_t)BATCH * HD * NPIX / 2],  g_CsL[(size_t)BATCH * HD * NPIX / 2];
__device__ uint32_t g_M2H[BATCH * CCH * HD / 2],   g_M2L[BATCH * CCH * HD / 2];
__device__ float g_G[BATCH * HD * HD];
__device__ float g_s[CCH];
__device__ float g_t[CCH];

// ---------------------------------------------------------------------------
__device__ __forceinline__ uint32_t smem_u32(const void* p) {
    uint32_t a;
    asm("{ .reg .u64 t; cvta.to.shared.u64 t, %1; cvt.u32.u64 %0, t; }" : "=r"(a) : "l"(p));
    return a;
}
__device__ __forceinline__ void bsplit(float x, __nv_bfloat16& h, __nv_bfloat16& l) {
    h = __float2bfloat16_rn(x);
    l = __float2bfloat16_rn(x - __bfloat162float(h));
}
__device__ __forceinline__ uint32_t packpair(__nv_bfloat16 a, __nv_bfloat16 b) {
    uint16_t au = *(uint16_t*)&a, bu = *(uint16_t*)&b;
    return (uint32_t)au | ((uint32_t)bu << 16);
}
__device__ __forceinline__ void cp16(uint32_t dst, const void* src) {
    asm volatile("cp.async.cg.shared.global [%0], [%1], 16;" :: "r"(dst), "l"(src));
}
#define SW128(off) ((off) ^ (((off) >> 3) & 0x70))

__device__ __forceinline__ void ldsm4(uint32_t (&r)[4], uint32_t addr) {
    asm volatile("ldmatrix.sync.aligned.m8n8.x4.shared.b16 {%0,%1,%2,%3}, [%4];"
                 : "=r"(r[0]), "=r"(r[1]), "=r"(r[2]), "=r"(r[3]) : "r"(addr));
}
__device__ __forceinline__ void ldsm4t(uint32_t (&r)[4], uint32_t addr) {
    asm volatile("ldmatrix.sync.aligned.m8n8.x4.trans.shared.b16 {%0,%1,%2,%3}, [%4];"
                 : "=r"(r[0]), "=r"(r[1]), "=r"(r[2]), "=r"(r[3]) : "r"(addr));
}
__device__ __forceinline__ void mma16(float4& d, const uint32_t* a, uint32_t b0, uint32_t b1) {
    asm volatile("mma.sync.aligned.m16n8k16.row.col.f32.bf16.bf16.f32 "
                 "{%0,%1,%2,%3},{%4,%5,%6,%7},{%8,%9},{%0,%1,%2,%3};"
                 : "+f"(d.x), "+f"(d.y), "+f"(d.z), "+f"(d.w)
                 : "r"(a[0]), "r"(a[1]), "r"(a[2]), "r"(a[3]), "r"(b0), "r"(b1));
}

// ---------------------------------------------------------------------------
// compute core: NP n16-groups per warp, BK=64, fragment reg double-buffering
// ---------------------------------------------------------------------------
static constexpr int SLAB_A = 16384;   // 128 rows x 128B

template<int NP, bool TRB>
__device__ __forceinline__ void compute_tile2(
    uint32_t abase, uint32_t ahalfoff,
    uint32_t bbase, uint32_t bhalfoff, int bchstride, int browoff,
    int lane, int wm, int wn, float4 (&acc)[2][NP][2]) {
    const int rl = lane & 15, gh = lane >> 4;
    constexpr int WN = NP * 16;

    uint32_t aH[2][2][4], aL[2][2][4];
    uint32_t bh[2][4], bl[2][4];

    auto loadA = [&](int ks, int buf) {
#pragma unroll
        for (int mt = 0; mt < 2; mt++) {
            uint32_t ar = abase + SW128((wm * 32 + mt * 16 + rl) * 128 + (ks * 2 + gh) * 16);
            ldsm4(aH[buf][mt], ar);
            ldsm4(aL[buf][mt], ar + ahalfoff);
        }
    };
    auto loadB = [&](int ks, int ntp, int buf) {
        if (!TRB) {
            uint32_t br = bbase + SW128((wn * WN + ntp * 16 + rl) * 128 + (ks * 2 + gh) * 16);
            ldsm4(bh[buf], br);
            ldsm4(bl[buf], br + bhalfoff);
        } else {
            int n = wn * WN + ntp * 16 + gh * 8;
            int chunk = n >> 6, col16 = (n & 63) >> 3;
            uint32_t br = bbase + chunk * bchstride +
                          SW128((browoff + ks * 16 + rl) * 128 + col16 * 16);
            ldsm4t(bh[buf], br);
            ldsm4t(bl[buf], br + bhalfoff);
        }
    };

    loadA(0, 0);
    loadB(0, 0, 0);
#pragma unroll
    for (int ks = 0; ks < 4; ks++) {
        const int ab = ks & 1;
#pragma unroll
        for (int ntp = 0; ntp < NP; ntp++) {
            const int bb = (ks * NP + ntp) & 1;
            if (ntp + 1 < NP) {
                loadB(ks, ntp + 1, (ks * NP + ntp + 1) & 1);
            } else if (ks + 1 < 4) {
                loadA(ks + 1, (ks + 1) & 1);
                loadB(ks + 1, 0, ((ks + 1) * NP) & 1);
            }
            uint32_t b0h[2], b1h[2], b0l[2], b1l[2];
#pragma unroll
            for (int j = 0; j < 2; j++) {
                b0h[j] = TRB ? bh[bb][2 * j]     : bh[bb][j];
                b1h[j] = TRB ? bh[bb][2 * j + 1] : bh[bb][j + 2];
                b0l[j] = TRB ? bl[bb][2 * j]     : bl[bb][j];
                b1l[j] = TRB ? bl[bb][2 * j + 1] : bl[bb][j + 2];
            }
#pragma unroll
            for (int j = 0; j < 2; j++)
#pragma unroll
                for (int mt = 0; mt < 2; mt++)
                    mma16(acc[mt][ntp][j], aH[ab][mt], b0h[j], b1h[j]);
#pragma unroll
            for (int j = 0; j < 2; j++)
#pragma unroll
                for (int mt = 0; mt < 2; mt++)
                    mma16(acc[mt][ntp][j], aH[ab][mt], b0l[j], b1l[j]);
#pragma unroll
            for (int j = 0; j < 2; j++)
#pragma unroll
                for (int mt = 0; mt < 2; mt++)
                    mma16(acc[mt][ntp][j], aL[ab][mt], b0h[j], b1h[j]);
        }
    }
}

// ---------------------------------------------------------------------------
// 256-thread GEMM stage: tile 128(M) x 64(N) x 64(K), stage = 48 KB
// ---------------------------------------------------------------------------
static constexpr int ST64   = 49152;
static constexpr int B_OFF  = 32768;
static constexpr int B_HALF = 8192;

__device__ __forceinline__ void loadA64(uint32_t bufb, int kofs,
                                        const __nv_bfloat16* aH, const __nv_bfloat16* aL, int sA) {
    const int tid = threadIdx.x;
#pragma unroll
    for (int i = 0; i < 8; i++) {
        int g = tid + i * 256;
        int row_lin = g >> 3, gran = g & 7;
        const __nv_bfloat16* s = (row_lin < 128) ? aH : aL;
        int row = row_lin & 127;
        uint32_t slaboff = (row_lin < 128) ? 0u : (uint32_t)SLAB_A;
        cp16(bufb + slaboff + SW128(row * 128 + gran * 16),
             s + (size_t)row * sA + kofs + gran * 8);
    }
}

// B loader, k-major rows (k3)
__device__ __forceinline__ void loadB64_n(uint32_t bufb, int kofs,
                                          const __nv_bfloat16* bH, const __nv_bfloat16* bL, int sB) {
    const int tid = threadIdx.x;
#pragma unroll
    for (int i = 0; i < 4; i++) {
        int g = tid + i * 256;
        int half = g >> 9, g3 = g & 511;
        int row = g3 >> 3, gran = g3 & 7;
        const __nv_bfloat16* s = half ? bL : bH;
        cp16(bufb + B_OFF + (uint32_t)half * B_HALF + SW128(row * 128 + gran * 16),
             s + (size_t)row * sB + kofs + gran * 8);
    }
}

// B loader, TRB (k5)
__device__ __forceinline__ void loadB64_t(uint32_t bufb, int kofs,
                                          const __nv_bfloat16* bH, const __nv_bfloat16* bL, int sB) {
    const int tid = threadIdx.x;
#pragma unroll
    for (int i = 0; i < 4; i++) {
        int g = tid + i * 256;
        int half = g >> 9, g3 = g & 511;
        int krow = g3 >> 3, gran = g3 & 7;
        const __nv_bfloat16* s = half ? bL : bH;
        cp16(bufb + B_OFF + (uint32_t)half * B_HALF + SW128(krow * 128 + gran * 16),
             s + (size_t)(kofs + krow) * sB + gran * 8);
    }
}

// ---------------------------------------------------------------------------
// prep
// ---------------------------------------------------------------------------
__global__ void __launch_bounds__(256) k_prep(const float* __restrict__ gamma,
                                              const float* __restrict__ beta,
                                              const float* __restrict__ mean,
                                              const float* __restrict__ var,
                                              const float* __restrict__ wA,
                                              const float* __restrict__ wB,
                                              const float* __restrict__ wC) {
    int idx = blockIdx.x * 256 + threadIdx.x;
    if (idx < BATCH * HD * HD) g_G[idx] = 0.0f;
    if (idx < CCH) {
        float inv = rsqrtf(var[idx] + 1e-5f);
        float sc  = inv * gamma[idx];
        g_s[idx] = sc;
        g_t[idx] = beta[idx] - mean[idx] * sc;
    }
    if (idx < 3 * HD * CCH / 2) {
        const float* src = (idx < 32768) ? wA : (idx < 65536) ? wB : wC;
        int lp = idx & 32767;
        float f0 = src[2 * lp], f1 = src[2 * lp + 1];
        __nv_bfloat16 h0, l0, h1, l1;
        bsplit(f0, h0, l0); bsplit(f1, h1, l1);
        g_WH[idx] = packpair(h0, h1);
        g_WL[idx] = packpair(l0, l1);
    }
}

// ---------------------------------------------------------------------------
// K1: logits = W[w] @ x[b], 256 threads, tile 128x64, direct-x fused split.
// ---------------------------------------------------------------------------
__device__ __forceinline__ void k1_ldg_B(float (&st)[16], const float* xb, int kofs) {
    const int tid = threadIdx.x;
#pragma unroll
    for (int i = 0; i < 4; i++) {
        int idx = tid + i * 256;
        int krow = idx >> 4, ng4 = idx & 15;
        const float* p = xb + (size_t)(kofs + krow) * NPIX + ng4 * 4;
        asm volatile("ld.global.nc.v4.f32 {%0,%1,%2,%3}, [%4];"
                     : "=f"(st[4 * i]), "=f"(st[4 * i + 1]),
                       "=f"(st[4 * i + 2]), "=f"(st[4 * i + 3]) : "l"(p));
    }
}

__device__ __forceinline__ void k1_sts_B(uint32_t bufb, const float (&st)[16]) {
    const int tid = threadIdx.x;
    const uint32_t bsb = bufb + B_OFF;
#pragma unroll
    for (int i = 0; i < 4; i++) {
        int idx = tid + i * 256;
        int krow = idx >> 4, ng4 = idx & 15;
        uint32_t off = bsb + SW128((uint32_t)(krow * 128 + ng4 * 8));
        __nv_bfloat16 h0, l0, h1, l1, h2, l2, h3, l3;
        bsplit(st[4 * i],     h0, l0);
        bsplit(st[4 * i + 1], h1, l1);
        bsplit(st[4 * i + 2], h2, l2);
        bsplit(st[4 * i + 3], h3, l3);
        uint32_t hi01 = packpair(h0, h1), hi23 = packpair(h2, h3);
        uint32_t lo01 = packpair(l0, l1), lo23 = packpair(l2, l3);
        asm volatile("st.shared.v2.u32 [%0], {%1,%2};"
                     :: "r"(off), "r"(hi01), "r"(hi23) : "memory");
        asm volatile("st.shared.v2.u32 [%0], {%1,%2};"
                     :: "r"(off + B_HALF), "r"(lo01), "r"(lo23) : "memory");
    }
}

__global__ void __launch_bounds__(256, 2) k1_gemm(const float* __restrict__ x) {
    extern __shared__ uint32_t smem[];
    uint32_t sbase = smem_u32(smem);
    const int b  = blockIdx.x / 192;
    const int r192 = blockIdx.x % 192;
    const int w  = r192 % 3;
    const int n0 = (r192 / 3) * 64;
    const int tid = threadIdx.x;
    const int lane = tid & 31, wid = tid >> 5;
    const int wm = wid & 3, wn = wid >> 2;

    float4 acc[2][2][2];
#pragma unroll
    for (int a = 0; a < 2; a++)
#pragma unroll
        for (int p = 0; p < 2; p++)
#pragma unroll
            for (int j = 0; j < 2; j++) acc[a][p][j] = make_float4(0.f, 0.f, 0.f, 0.f);

    const __nv_bfloat16* aH = (const __nv_bfloat16*)g_WH + (size_t)w * HD * CCH;
    const __nv_bfloat16* aL = (const __nv_bfloat16*)g_WL + (size_t)w * HD * CCH;
    const float* xb = x + (size_t)b * CCH * NPIX + n0;

    const int KT = CCH / 64;   // 8
    float st[16];

    k1_ldg_B(st, xb, 0);
    loadA64(sbase, 0, aH, aL, CCH);
    asm volatile("cp.async.commit_group;" ::: "memory");
    k1_sts_B(sbase, st);

    for (int kt = 0; kt < KT; kt++) {
        asm volatile("cp.async.wait_group 0;" ::: "memory");
        __syncthreads();
        if (kt + 1 < KT) {
            k1_ldg_B(st, xb, (kt + 1) * 64);
            loadA64(sbase + ((kt + 1) & 1) * ST64, (kt + 1) * 64, aH, aL, CCH);
            asm volatile("cp.async.commit_group;" ::: "memory");
        }
        uint32_t bufb = sbase + (kt & 1) * ST64;
        compute_tile2<2, true>(bufb, SLAB_A, bufb + B_OFF, B_HALF,
                               B_HALF, 0, lane, wm, wn, acc);
        if (kt + 1 < KT)
            k1_sts_B(sbase + ((kt + 1) & 1) * ST64, st);
    }

#pragma unroll
    for (int mt = 0; mt < 2; mt++)
#pragma unroll
        for (int ntp = 0; ntp < 2; ntp++)
#pragma unroll
            for (int j = 0; j < 2; j++) {
                int r = wm * 32 + mt * 16 + (lane >> 2);
                int c = wn * 32 + ntp * 16 + j * 8 + (lane & 3) * 2;
                float4 v = acc[mt][ntp][j];
                if (w == 1) {
                    uint32_t* DH0 = g_BfH + ((size_t)b * HD + r) * (NPIX / 2) + (n0 + c) / 2;
                    uint32_t* DL0 = g_BfL + ((size_t)b * HD + r) * (NPIX / 2) + (n0 + c) / 2;
                    uint32_t* DH1 = DH0 + 8 * (NPIX / 2);
                    uint32_t* DL1 = DL0 + 8 * (NPIX / 2);
                    __nv_bfloat16 h0, l0, h1, l1;
                    bsplit(v.x, h0, l0); bsplit(v.y, h1, l1);
                    *DH0 = packpair(h0, h1); *DL0 = packpair(l0, l1);
                    bsplit(v.z, h0, l0); bsplit(v.w, h1, l1);
                    *DH1 = packpair(h0, h1); *DL1 = packpair(l0, l1);
                } else {
                    const int wlog = (w == 0) ? 0 : 1;
                    float* D = g_logits + (((size_t)wlog * BATCH + b) * HD + r) * NPIX + n0 + c;
                    *(float2*)D              = make_float2(v.x, v.y);
                    *(float2*)(D + 8 * NPIX) = make_float2(v.z, v.w);
                }
            }
}

// ---------------------------------------------------------------------------
// K2: row softmax with shuffle reductions
// ---------------------------------------------------------------------------
__global__ void __launch_bounds__(256) k_softmax() {
    int rid = blockIdx.x;                       // 0..4095
    int wlog = (rid < 2048) ? 0 : 1;
    int r = rid & 2047;                         // b*128 + h
    const float* p = g_logits + ((size_t)(wlog * 2048 + r)) * NPIX;
    int tid = threadIdx.x;
    const int lane = tid & 31, wrp = tid >> 5;
    __shared__ float wred[8];

    float4 v[4];
#pragma unroll
    for (int q = 0; q < 4; q++) v[q] = *(const float4*)(p + (q * 256 + tid) * 4);

    float m = v[0].x;
#pragma unroll
    for (int q = 0; q < 4; q++) {
        m = fmaxf(m, v[q].x); m = fmaxf(m, v[q].y);
        m = fmaxf(m, v[q].z); m = fmaxf(m, v[q].w);
    }
#pragma unroll
    for (int off = 16; off > 0; off >>= 1)
        m = fmaxf(m, __shfl_xor_sync(0xffffffffu, m, off));
    if (lane == 0) wred[wrp] = m;
    __syncthreads();
    float M = wred[0];
#pragma unroll
    for (int i = 1; i < 8; i++) M = fmaxf(M, wred[i]);
    __syncthreads();

    float ssum = 0.0f;
#pragma unroll
    for (int q = 0; q < 4; q++) {
        v[q].x = expf(v[q].x - M); ssum += v[q].x;
        v[q].y = expf(v[q].y - M); ssum += v[q].y;
        v[q].z = expf(v[q].z - M); ssum += v[q].z;
        v[q].w = expf(v[q].w - M); ssum += v[q].w;
    }
#pragma unroll
    for (int off = 16; off > 0; off >>= 1)
        ssum += __shfl_xor_sync(0xffffffffu, ssum, off);
    if (lane == 0) wred[wrp] = ssum;
    __syncthreads();
    float S = 0.0f;
#pragma unroll
    for (int i = 0; i < 8; i++) S += wred[i];
    float inv = 1.0f / S;

    uint32_t* AH = (wlog == 0 ? g_AmH : g_CsH) + (size_t)r * (NPIX / 2);
    uint32_t* AL = (wlog == 0 ? g_AmL : g_CsL) + (size_t)r * (NPIX / 2);
#pragma unroll
    for (int q = 0; q < 4; q++) {
        int n2 = (q * 256 + tid) * 2;
        float a0 = v[q].x * inv, a1 = v[q].y * inv;
        float a2 = v[q].z * inv, a3 = v[q].w * inv;
        __nv_bfloat16 h0, l0, h1, l1;
        bsplit(a0, h0, l0); bsplit(a1, h1, l1);
        AH[n2] = packpair(h0, h1); AL[n2] = packpair(l0, l1);
        bsplit(a2, h0, l0); bsplit(a3, h1, l1);
        AH[n2 + 1] = packpair(h0, h1); AL[n2 + 1] = packpair(l0, l1);
    }
}

// ---------------------------------------------------------------------------
// K3: G[b] += Bf[b] @ Am[b]^T, 256 threads, tile 128x64, 8-way k-split.
// grid (16 b, 16 = 8 ksplit x 2 n-half)
// ---------------------------------------------------------------------------
__global__ void __launch_bounds__(256, 2) k3_gemm() {
    extern __shared__ uint32_t smem[];
    uint32_t sbase = smem_u32(smem);
    const int b  = blockIdx.x;
    const int kb = (blockIdx.y >> 1) * 512;
    const int nh = (blockIdx.y & 1) * 64;
    const int tid = threadIdx.x;
    const int lane = tid & 31, wid = tid >> 5;
    const int wm = wid & 3, wn = wid >> 2;

    float4 acc[2][2][2];
#pragma unroll
    for (int a = 0; a < 2; a++)
#pragma unroll
        for (int p = 0; p < 2; p++)
#pragma unroll
            for (int j = 0; j < 2; j++) acc[a][p][j] = make_float4(0.f, 0.f, 0.f, 0.f);

    const __nv_bfloat16* aH = (const __nv_bfloat16*)g_BfH + (size_t)b * HD * NPIX + kb;
    const __nv_bfloat16* aL = (const __nv_bfloat16*)g_BfL + (size_t)b * HD * NPIX + kb;
    const __nv_bfloat16* bH = (const __nv_bfloat16*)g_AmH + ((size_t)b * HD + nh) * NPIX + kb;
    const __nv_bfloat16* bL = (const __nv_bfloat16*)g_AmL + ((size_t)b * HD + nh) * NPIX + kb;

    const int KT = 8;   // 512 / 64
    loadA64(sbase, 0, aH, aL, NPIX);
    loadB64_n(sbase, 0, bH, bL, NPIX);
    asm volatile("cp.async.commit_group;" ::: "memory");

    for (int kt = 0; kt < KT; kt++) {
        asm volatile("cp.async.wait_group 0;" ::: "memory");
        __syncthreads();
        if (kt + 1 < KT) {
            loadA64(sbase + ((kt + 1) & 1) * ST64, (kt + 1) * 64, aH, aL, NPIX);
            loadB64_n(sbase + ((kt + 1) & 1) * ST64, (kt + 1) * 64, bH, bL, NPIX);
            asm volatile("cp.async.commit_group;" ::: "memory");
        }
        uint32_t bufb = sbase + (kt & 1) * ST64;
        compute_tile2<2, false>(bufb, SLAB_A, bufb + B_OFF, B_HALF,
                                B_HALF, 0, lane, wm, wn, acc);
    }

    float* Gp = g_G + (size_t)b * HD * HD;
#pragma unroll
    for (int mt = 0; mt < 2; mt++)
#pragma unroll
        for (int ntp = 0; ntp < 2; ntp++)
#pragma unroll
            for (int j = 0; j < 2; j++) {
                int r = wm * 32 + mt * 16 + (lane >> 2);
                int c = nh + wn * 32 + ntp * 16 + j * 8 + (lane & 3) * 2;
                float4 v = acc[mt][ntp][j];
                atomicAdd(&Gp[r * HD + c],           v.x);
                atomicAdd(&Gp[r * HD + c + 1],       v.y);
                atomicAdd(&Gp[(r + 8) * HD + c],     v.z);
                atomicAdd(&Gp[(r + 8) * HD + c + 1], v.w);
            }
}

// ---------------------------------------------------------------------------
// K4: M2 = (s .* wProj) @ G  -> bf16 hi/lo [b][c][g]
// ---------------------------------------------------------------------------
__global__ void __launch_bounds__(256) k_M2t(const float* __restrict__ wProj) {
    __shared__ float As[16][128];
    __shared__ float Bs[16][128];
    const int b  = blockIdx.x;
    const int c0 = blockIdx.y * 128;
    const float* Gp = g_G + (size_t)b * HD * HD;
    const int tid = threadIdx.x;
    const int tx = tid & 15, ty = tid >> 4;

    float acc[8][8];
#pragma unroll
    for (int i = 0; i < 8; i++)
#pragma unroll
        for (int j = 0; j < 8; j++) acc[i][j] = 0.0f;

    for (int k0 = 0; k0 < HD; k0 += 16) {
#pragma unroll
        for (int s = tid; s < 512; s += 256) {
            int row = s >> 2, kq = (s & 3) << 2;
            float4 v = *(const float4*)(wProj + (size_t)(c0 + row) * HD + k0 + kq);
            As[kq + 0][row] = v.x; As[kq + 1][row] = v.y;
            As[kq + 2][row] = v.z; As[kq + 3][row] = v.w;
            int kr = s >> 5, nq = (s & 31) << 2;
            *(float4*)&Bs[kr][nq] = *(const float4*)(Gp + (size_t)(k0 + kr) * HD + nq);
        }
        __syncthreads();
#pragma unroll
        for (int k = 0; k < 16; k++) {
            float a[8], bb[8];
            *(float4*)(a)      = *(const float4*)&As[k][ty * 8];
            *(float4*)(a + 4)  = *(const float4*)&As[k][ty * 8 + 4];
            *(float4*)(bb)     = *(const float4*)&Bs[k][tx * 8];
            *(float4*)(bb + 4) = *(const float4*)&Bs[k][tx * 8 + 4];
#pragma unroll
            for (int i = 0; i < 8; i++)
#pragma unroll
                for (int j = 0; j < 8; j++) acc[i][j] = fmaf(a[i], bb[j], acc[i][j]);
        }
        __syncthreads();
    }
#pragma unroll
    for (int i = 0; i < 8; i++) {
        int c = c0 + ty * 8 + i;
        float sc = g_s[c];
        uint32_t* DH = g_M2H + ((size_t)b * CCH + c) * (HD / 2) + tx * 4;
        uint32_t* DL = g_M2L + ((size_t)b * CCH + c) * (HD / 2) + tx * 4;
#pragma unroll
        for (int j = 0; j < 4; j++) {
            float f0 = sc * acc[i][2 * j], f1 = sc * acc[i][2 * j + 1];
            __nv_bfloat16 h0, l0, h1, l1;
            bsplit(f0, h0, l0); bsplit(f1, h1, l1);
            DH[j] = packpair(h0, h1);
            DL[j] = packpair(l0, l1);
        }
    }
}

// ---------------------------------------------------------------------------
// K5: out[b] = M2[b] @ Cs[b] + t.  256 threads, tile 128(c)x64(n), KT=2,
// 2 CTAs/SM.  c-tile fastest in grid for Cs L2 reuse.
// ---------------------------------------------------------------------------
__global__ void __launch_bounds__(256, 2) k5_gemm(float* __restrict__ out) {
    extern __shared__ uint32_t smem[];
    uint32_t sbase = smem_u32(smem);
    const int b  = blockIdx.y;
    const int c0 = (blockIdx.x & 3) * 128;
    const int n0 = (blockIdx.x >> 2) * 64;
    const int tid = threadIdx.x;
    const int lane = tid & 31, wid = tid >> 5;
    const int wm = wid & 3, wn = wid >> 2;

    float4 acc[2][2][2];
#pragma unroll
    for (int a = 0; a < 2; a++)
#pragma unroll
        for (int p = 0; p < 2; p++)
#pragma unroll
            for (int j = 0; j < 2; j++) acc[a][p][j] = make_float4(0.f, 0.f, 0.f, 0.f);

    const __nv_bfloat16* aH = (const __nv_bfloat16*)g_M2H + ((size_t)b * CCH + c0) * HD;
    const __nv_bfloat16* aL = (const __nv_bfloat16*)g_M2L + ((size_t)b * CCH + c0) * HD;
    const __nv_bfloat16* bH = (const __nv_bfloat16*)g_CsH + (size_t)b * HD * NPIX + n0;
    const __nv_bfloat16* bL = (const __nv_bfloat16*)g_CsL + (size_t)b * HD * NPIX + n0;

    const int KT = 2;   // 128 / 64
    loadA64(sbase, 0, aH, aL, HD);
    loadB64_t(sbase, 0, bH, bL, NPIX);
    asm volatile("cp.async.commit_group;" ::: "memory");

    for (int kt = 0; kt < KT; kt++) {
        asm volatile("cp.async.wait_group 0;" ::: "memory");
        __syncthreads();
        if (kt + 1 < KT) {
            loadA64(sbase + ((kt + 1) & 1) * ST64, (kt + 1) * 64, aH, aL, HD);
            loadB64_t(sbase + ((kt + 1) & 1) * ST64, (kt + 1) * 64, bH, bL, NPIX);
            asm volatile("cp.async.commit_group;" ::: "memory");
        }
        uint32_t bufb = sbase + (kt & 1) * ST64;
        compute_tile2<2, true>(bufb, SLAB_A, bufb + B_OFF, B_HALF,
                               B_HALF, 0, lane, wm, wn, acc);
    }

#pragma unroll
    for (int mt = 0; mt < 2; mt++)
#pragma unroll
        for (int ntp = 0; ntp < 2; ntp++)
#pragma unroll
            for (int j = 0; j < 2; j++) {
                int r = wm * 32 + mt * 16 + (lane >> 2);
                int c = wn * 32 + ntp * 16 + j * 8 + (lane & 3) * 2;
                float4 v = acc[mt][ntp][j];
                float t0 = g_t[c0 + r];
                float t1 = g_t[c0 + r + 8];
                float* D = out + ((size_t)b * CCH + c0 + r) * NPIX + n0 + c;
                *(float2*)D              = make_float2(v.x + t0, v.y + t0);
                *(float2*)(D + 8 * NPIX) = make_float2(v.z + t1, v.w + t1);
            }
}

// ---------------------------------------------------------------------------
extern "C" void kernel_launch(void* const* d_in, const int* in_sizes, int n_in,
                              void* d_out, int out_size) {
    const float* x     = (const float*)d_in[0];
    const float* wA    = (const float*)d_in[1];
    const float* wB    = (const float*)d_in[2];
    const float* wC    = (const float*)d_in[3];
    const float* wProj = (const float*)d_in[4];
    const float* gamma = (const float*)d_in[5];
    const float* beta  = (const float*)d_in[6];
    const float* mean  = (const float*)d_in[7];
    const float* var   = (const float*)d_in[8];
    float* out = (float*)d_out;

    const int smem_64 = 2 * ST64;               // 96 KB  (2 CTAs/SM)
    cudaFuncSetAttribute(k1_gemm, cudaFuncAttributeMaxDynamicSharedMemorySize, smem_64);
    cudaFuncSetAttribute(k3_gemm, cudaFuncAttributeMaxDynamicSharedMemorySize, smem_64);
    cudaFuncSetAttribute(k5_gemm, cudaFuncAttributeMaxDynamicSharedMemorySize, smem_64);

    k_prep<<<1024, 256>>>(gamma, beta, mean, var, wA, wB, wC);
    k1_gemm<<<dim3(3072, 1, 1), 256, smem_64>>>(x);
    k_softmax<<<4096, 256>>>();
    k3_gemm<<<dim3(BATCH, 16), 256, smem_64>>>();
    k_M2t<<<dim3(BATCH, CCH / 128), 256>>>(wProj);
    k5_gemm<<<dim3(256, BATCH, 1), 256, smem_64>>>(out);
}